// round 13
// baseline (speedup 1.0000x reference)
#include <cuda_runtime.h>
#include <cuda_bf16.h>
#include <cstdint>

#define NB 2
#define SS 2048
#define DD 1024
#define NH 16
#define HD 64
#define MM (NB*SS)
#define KTOT 3072   // 3x K-expansion for bf16 hi/lo compensation

// ---------------------------------------------------------------------------
// Scratch (__device__ globals; allocation-free rule)
// ---------------------------------------------------------------------------
__device__ __nv_bfloat16 g_xs[(size_t)MM*KTOT];        // x split-expanded [M][3K]
__device__ __nv_bfloat16 g_zs[(size_t)MM*KTOT];        // z split-expanded [M][3K]
__device__ __nv_bfloat16 g_ws[4][(size_t)DD*KTOT];     // W transposed+split [N][3K]
__device__ __nv_bfloat16 g_qx[(size_t)NB*NH*SS*192];   // Q [bh][s][qh|qh|ql], pre-scaled 1/8
__device__ __nv_bfloat16 g_kx[(size_t)NB*NH*SS*192];   // K [bh][s][kh|kl|kh]
__device__ __nv_bfloat16 g_vx[(size_t)NB*NH*3*SS*HD];  // V [bh][vh rows | vl rows | vh rows][hd]

// ---------------------------------------------------------------------------
// Helpers (sm_100-safe PTX: cp.async / ldmatrix / mma.sync)
// ---------------------------------------------------------------------------
__device__ __forceinline__ uint32_t smem_u32(const void* p) {
    uint32_t a;
    asm("{ .reg .u64 t; cvta.to.shared.u64 t, %1; cvt.u32.u64 %0, t; }" : "=r"(a) : "l"(p));
    return a;
}
__device__ __forceinline__ void cp16(uint32_t s, const void* g) {
    asm volatile("cp.async.cg.shared.global [%0], [%1], 16;" :: "r"(s), "l"(g));
}
__device__ __forceinline__ void ldsm_x4(uint32_t (&r)[4], uint32_t a) {
    asm volatile("ldmatrix.sync.aligned.m8n8.x4.shared.b16 {%0,%1,%2,%3}, [%4];"
                 : "=r"(r[0]), "=r"(r[1]), "=r"(r[2]), "=r"(r[3]) : "r"(a));
}
__device__ __forceinline__ void ldsm_x4t(uint32_t (&r)[4], uint32_t a) {
    asm volatile("ldmatrix.sync.aligned.m8n8.x4.trans.shared.b16 {%0,%1,%2,%3}, [%4];"
                 : "=r"(r[0]), "=r"(r[1]), "=r"(r[2]), "=r"(r[3]) : "r"(a));
}
__device__ __forceinline__ void ldsm_x2(uint32_t (&r)[2], uint32_t a) {
    asm volatile("ldmatrix.sync.aligned.m8n8.x2.shared.b16 {%0,%1}, [%2];"
                 : "=r"(r[0]), "=r"(r[1]) : "r"(a));
}
__device__ __forceinline__ void mma_bf16(float (&c)[4], const uint32_t (&a)[4],
                                         uint32_t b0, uint32_t b1) {
    asm volatile("mma.sync.aligned.m16n8k16.row.col.f32.bf16.bf16.f32 "
                 "{%0,%1,%2,%3}, {%4,%5,%6,%7}, {%8,%9}, {%0,%1,%2,%3};"
                 : "+f"(c[0]), "+f"(c[1]), "+f"(c[2]), "+f"(c[3])
                 : "r"(a[0]), "r"(a[1]), "r"(a[2]), "r"(a[3]), "r"(b0), "r"(b1));
}
__device__ __forceinline__ uint32_t bfpack(float a, float b) {
    __nv_bfloat162 t = __floats2bfloat162_rn(a, b);
    return *reinterpret_cast<uint32_t*>(&t);
}
__device__ __forceinline__ float bfres(float a) {
    return a - __bfloat162float(__float2bfloat16(a));
}
// exp on the FMA/ALU pipes (no MUFU). Valid for x <= 0; flushes to ~0 below -87.
__device__ __forceinline__ float fexp(float x) {
    float y = x * 1.4426950408889634f;
    y = fmaxf(y, -126.0f);
    float t = y + 12582912.0f;            // round-to-nearest-int (magic)
    int   i = __float_as_int(t);
    float f = y - (t - 12582912.0f);      // frac in [-0.5, 0.5]
    float p = fmaf(f, 1.3333558146e-3f, 9.6181291076e-3f);
    p = fmaf(f, p, 5.5504108664e-2f);
    p = fmaf(f, p, 2.4022650696e-1f);
    p = fmaf(f, p, 6.9314718056e-1f);
    p = fmaf(f, p, 1.0f);
    return p * __int_as_float((i + 127) << 23);
}

// ---------------------------------------------------------------------------
// Conversions
// ---------------------------------------------------------------------------
__global__ void conv_split(const float* __restrict__ xin) {
    size_t idx = (size_t)blockIdx.x * 256 + threadIdx.x;
    int m = (int)(idx >> 10), kk = (int)(idx & 1023);
    float v = xin[idx];
    __nv_bfloat16 hi = __float2bfloat16(v);
    __nv_bfloat16 lo = __float2bfloat16(v - __bfloat162float(hi));
    __nv_bfloat16* row = g_xs + (size_t)m * KTOT;
    row[kk] = hi; row[1024 + kk] = hi; row[2048 + kk] = lo;
}

// W[K,N] -> g_ws[z][N][3K]: seg0 = hi, seg1 = lo, seg2 = hi
__global__ void conv_w(const float* __restrict__ W0, const float* __restrict__ W1,
                       const float* __restrict__ W2, const float* __restrict__ W3) {
    __shared__ float t[32][33];
    const int z = blockIdx.z;
    const float* W = (z == 0) ? W0 : (z == 1) ? W1 : (z == 2) ? W2 : W3;
    __nv_bfloat16* O = g_ws[z];
    int tx = threadIdx.x, ty = threadIdx.y;
    int k0 = blockIdx.y * 32, n0 = blockIdx.x * 32;
#pragma unroll
    for (int i = 0; i < 4; i++) {
        int kk = ty * 4 + i;
        t[kk][tx] = W[(size_t)(k0 + kk) * DD + n0 + tx];
    }
    __syncthreads();
#pragma unroll
    for (int i = 0; i < 4; i++) {
        int n = n0 + ty * 4 + i;
        int k = k0 + tx;
        float v = t[tx][ty * 4 + i];
        __nv_bfloat16 hi = __float2bfloat16(v);
        __nv_bfloat16 lo = __float2bfloat16(v - __bfloat162float(hi));
        __nv_bfloat16* row = O + (size_t)n * KTOT;
        row[k] = hi; row[2048 + k] = hi; row[1024 + k] = lo;
    }
}

// ---------------------------------------------------------------------------
// mma.sync bf16 GEMM: C[4096,1024] over K=3072. 128x128 CTA, 8 warps.
// K-chunk 64, 2-stage cp.async pipeline, dynamic smem (rows padded to 72 bf16).
// MODE 0: A=g_xs, B=g_ws[z]; epilogue splits into g_qx/g_kx/g_vx (bf16 hi/lo)
// MODE 1: A=g_zs, B=g_ws[3]; epilogue = Cout + bias (fp32)
// ---------------------------------------------------------------------------
#define GBK 64
#define NCH (KTOT / GBK)        // 48
#define GPAD 72                 // elements per smem row (144 B)
#define GSTG (128 * GPAD * 2)   // bytes per stage per matrix = 18432
#define GSMEM (4 * GSTG)        // 73728

template<int MODE>
__global__ __launch_bounds__(256)
void mma_gemm(const float* __restrict__ bias, float* __restrict__ Cout) {
    extern __shared__ __align__(16) char gs[];
    const uint32_t sAu = smem_u32(gs);
    const uint32_t sBu = sAu + 2 * GSTG;

    const int tid = threadIdx.x;
    const int wid = tid >> 5, lane = tid & 31;
    const int wm = wid >> 2;
    const int wn = wid & 3;

    const __nv_bfloat16* A = (MODE == 0) ? g_xs : g_zs;
    const __nv_bfloat16* B = (MODE == 0) ? g_ws[blockIdx.z] : g_ws[3];
    const __nv_bfloat16* Ab = A + (size_t)blockIdx.y * 128 * KTOT;
    const __nv_bfloat16* Bb = B + (size_t)blockIdx.x * 128 * KTOT;

    const int lr = tid >> 3;            // 0..31 (+32 per t)
    const int lce = (tid & 7) * 8;      // element col
    const int lcb = lce * 2;            // byte col

    float acc[4][4][4];
#pragma unroll
    for (int i = 0; i < 4; i++)
#pragma unroll
        for (int j = 0; j < 4; j++)
#pragma unroll
            for (int v = 0; v < 4; v++) acc[i][j][v] = 0.f;

    auto load_chunk = [&](int chunk, int s) {
        const __nv_bfloat16* Ak = Ab + (size_t)chunk * GBK;
        const __nv_bfloat16* Bk = Bb + (size_t)chunk * GBK;
#pragma unroll
        for (int t = 0; t < 4; t++) {
            int row = lr + t * 32;
            cp16(sAu + s * GSTG + row * (GPAD * 2) + lcb, Ak + (size_t)row * KTOT + lce);
            cp16(sBu + s * GSTG + row * (GPAD * 2) + lcb, Bk + (size_t)row * KTOT + lce);
        }
    };

    load_chunk(0, 0);
    asm volatile("cp.async.commit_group;");

    for (int i = 0; i < NCH; i++) {
        const int s = i & 1;
        if (i + 1 < NCH) {
            load_chunk(i + 1, (i + 1) & 1);
            asm volatile("cp.async.commit_group;");
            asm volatile("cp.async.wait_group 1;");
        } else {
            asm volatile("cp.async.wait_group 0;");
        }
        __syncthreads();

#pragma unroll
        for (int k0 = 0; k0 < GBK; k0 += 16) {
            uint32_t afr[4][4];
#pragma unroll
            for (int mi = 0; mi < 4; mi++) {
                int row = wm * 64 + mi * 16 + (lane & 15);
                int col = k0 + (lane >> 4) * 8;
                ldsm_x4(afr[mi], sAu + s * GSTG + (row * GPAD + col) * 2);
            }
            uint32_t bfr[4][2];
#pragma unroll
            for (int ni = 0; ni < 4; ni++) {
                int l = lane & 15;
                int row = wn * 32 + ni * 8 + (l & 7);
                int col = k0 + (l >> 3) * 8;
                ldsm_x2(bfr[ni], sBu + s * GSTG + (row * GPAD + col) * 2);
            }
#pragma unroll
            for (int mi = 0; mi < 4; mi++)
#pragma unroll
                for (int ni = 0; ni < 4; ni++)
                    mma_bf16(acc[mi][ni], afr[mi], bfr[ni][0], bfr[ni][1]);
        }
        __syncthreads();
    }

    // Epilogue
    const int qr = lane >> 2, qc = (lane & 3) * 2;
#pragma unroll
    for (int mi = 0; mi < 4; mi++) {
#pragma unroll
        for (int ni = 0; ni < 4; ni++) {
            int col  = blockIdx.x * 128 + wn * 32 + ni * 8 + qc;
            int row0 = blockIdx.y * 128 + wm * 64 + mi * 16 + qr;
            int row1 = row0 + 8;
            float v0 = acc[mi][ni][0], v1 = acc[mi][ni][1];
            float v2 = acc[mi][ni][2], v3 = acc[mi][ni][3];
            if (MODE == 0) {
                const int z = blockIdx.z;
                if (z == 0) { v0 *= 0.125f; v1 *= 0.125f; v2 *= 0.125f; v3 *= 0.125f; }
                int h = col >> 6, hd = col & 63;
                int b0 = row0 >> 11, s0 = row0 & (SS - 1);
                int b1 = row1 >> 11, s1 = row1 & (SS - 1);
                int bh0 = b0 * NH + h, bh1 = b1 * NH + h;
                uint32_t H01 = bfpack(v0, v1), L01 = bfpack(bfres(v0), bfres(v1));
                uint32_t H23 = bfpack(v2, v3), L23 = bfpack(bfres(v2), bfres(v3));
                if (z == 0) {
                    __nv_bfloat16* p0 = g_qx + ((size_t)bh0 * SS + s0) * 192 + hd;
                    __nv_bfloat16* p1 = g_qx + ((size_t)bh1 * SS + s1) * 192 + hd;
                    *(uint32_t*)p0 = H01; *(uint32_t*)(p0 + 64) = H01; *(uint32_t*)(p0 + 128) = L01;
                    *(uint32_t*)p1 = H23; *(uint32_t*)(p1 + 64) = H23; *(uint32_t*)(p1 + 128) = L23;
                } else if (z == 1) {
                    __nv_bfloat16* p0 = g_kx + ((size_t)bh0 * SS + s0) * 192 + hd;
                    __nv_bfloat16* p1 = g_kx + ((size_t)bh1 * SS + s1) * 192 + hd;
                    *(uint32_t*)p0 = H01; *(uint32_t*)(p0 + 64) = L01; *(uint32_t*)(p0 + 128) = H01;
                    *(uint32_t*)p1 = H23; *(uint32_t*)(p1 + 64) = L23; *(uint32_t*)(p1 + 128) = H23;
                } else {
                    __nv_bfloat16* p0 = g_vx + ((size_t)bh0 * 3 * SS + s0) * HD + hd;
                    __nv_bfloat16* p1 = g_vx + ((size_t)bh1 * 3 * SS + s1) * HD + hd;
                    *(uint32_t*)p0 = H01; *(uint32_t*)(p0 + SS * HD) = L01; *(uint32_t*)(p0 + 2 * SS * HD) = H01;
                    *(uint32_t*)p1 = H23; *(uint32_t*)(p1 + SS * HD) = L23; *(uint32_t*)(p1 + 2 * SS * HD) = H23;
                }
            } else {
                float bx0 = bias[col], bx1 = bias[col + 1];
                *(float2*)(Cout + (size_t)row0 * DD + col) = make_float2(v0 + bx0, v1 + bx1);
                *(float2*)(Cout + (size_t)row1 * DD + col) = make_float2(v2 + bx0, v3 + bx1);
            }
        }
    }
}

// ---------------------------------------------------------------------------
// Flash attention on mma.sync. 64 q-rows/CTA, 4 warps (warp = 16 rows).
// QK over K'=192 (hi/lo), PV over 192 (P hi/lo x V hi/lo). exp on FMA pipe.
// 2-stage cp.async pipeline on K/V.
// smem: K 2x[64][200] bf16 (2x25600 B), V 2x[192][72] bf16 (2x27648 B).
// ---------------------------------------------------------------------------
#define KSTR 400           // bytes per K/Q smem row
#define VSTR 144           // bytes per V smem row
#define KSTG 25600
#define VSTG 27648
#define FSMEM (2 * KSTG + 2 * VSTG)   // 106496

__global__ __launch_bounds__(128, 2)
void flash_mma() {
    extern __shared__ __align__(16) char fs[];
    const uint32_t kb = smem_u32(fs);          // 2 K stages
    const uint32_t vb = kb + 2 * KSTG;         // 2 V stages
    const int tid = threadIdx.x, w = tid >> 5, lane = tid & 31;
    const int qb = gridDim.x - 1 - blockIdx.x;    // heavy CTAs first
    const int bh = blockIdx.y;

    const __nv_bfloat16* Qg = g_qx + ((size_t)bh * SS + qb * 64) * 192;
    const __nv_bfloat16* Kg = g_kx + (size_t)bh * SS * 192;
    const __nv_bfloat16* Vg = g_vx + (size_t)bh * 3 * SS * HD;

    // ldmatrix per-lane offsets
    const int ra = lane & 15, ca = (lane >> 4) << 3;               // A (rows of Q)
    const int rb = (lane & 7) + ((lane >> 1) & 8), cb = lane & 8;  // B for QK (rows of K)
    const int rv = lane & 15, cv = (lane >> 4) << 3;               // B for PV (trans)

    // ---- Q into K stage 0, extract a-frags ----
    uint32_t qfr[12][4];
#pragma unroll
    for (int t = 0; t < 12; t++) {
        int idx = tid + t * 128;
        int r = idx / 24, c = idx - r * 24;
        cp16(kb + r * KSTR + c * 16, Qg + (size_t)r * 192 + c * 8);
    }
    asm volatile("cp.async.commit_group;");
    asm volatile("cp.async.wait_group 0;");
    __syncthreads();
#pragma unroll
    for (int k = 0; k < 12; k++)
        ldsm_x4(qfr[k], kb + (16 * w + ra) * KSTR + (k * 16 + ca) * 2);
    __syncthreads();   // everyone has Q frags; K stage 0 reusable

    auto load_kv = [&](int kt, int s) {
#pragma unroll
        for (int t = 0; t < 12; t++) {
            int idx = tid + t * 128;
            int r = idx / 24, c = idx - r * 24;
            cp16(kb + s * KSTG + r * KSTR + c * 16, Kg + (size_t)(kt * 64 + r) * 192 + c * 8);
        }
#pragma unroll
        for (int t = 0; t < 12; t++) {
            int idx = tid + t * 128;
            int r = idx >> 3, c = idx & 7;       // r in 0..191
            int seg = r >> 6, rr = r & 63;
            cp16(vb + s * VSTG + r * VSTR + c * 16, Vg + (size_t)(seg * SS + kt * 64 + rr) * HD + c * 8);
        }
    };

    float m0 = -1e30f, m1 = -1e30f, l0 = 0.f, l1 = 0.f;
    float o[8][4];
#pragma unroll
    for (int j = 0; j < 8; j++)
#pragma unroll
        for (int v = 0; v < 4; v++) o[j][v] = 0.f;

    load_kv(0, 0);
    asm volatile("cp.async.commit_group;");

    for (int kt = 0; kt <= qb; kt++) {
        const int s = kt & 1;
        if (kt < qb) {
            load_kv(kt + 1, s ^ 1);
            asm volatile("cp.async.commit_group;");
            asm volatile("cp.async.wait_group 1;");
        } else {
            asm volatile("cp.async.wait_group 0;");
        }
        __syncthreads();
        const uint32_t kbs = kb + s * KSTG;
        const uint32_t vbs = vb + s * VSTG;

        // ---- S = Q K'^T ----
        float sf[8][4];
#pragma unroll
        for (int j = 0; j < 8; j++)
#pragma unroll
            for (int v = 0; v < 4; v++) sf[j][v] = 0.f;
#pragma unroll
        for (int jj = 0; jj < 4; jj++) {
#pragma unroll
            for (int k = 0; k < 12; k++) {
                uint32_t r4[4];
                ldsm_x4(r4, kbs + (16 * jj + rb) * KSTR + (k * 16 + cb) * 2);
                mma_bf16(sf[2 * jj],     qfr[k], r4[0], r4[1]);
                mma_bf16(sf[2 * jj + 1], qfr[k], r4[2], r4[3]);
            }
        }

        // ---- causal mask on diagonal tile ----
        if (kt == qb) {
            int row0 = 16 * w + (lane >> 2);
#pragma unroll
            for (int j = 0; j < 8; j++) {
                int key = 8 * j + 2 * (lane & 3);
                if (key     > row0)     sf[j][0] = -1e30f;
                if (key + 1 > row0)     sf[j][1] = -1e30f;
                if (key     > row0 + 8) sf[j][2] = -1e30f;
                if (key + 1 > row0 + 8) sf[j][3] = -1e30f;
            }
        }

        // ---- online softmax ----
        float tm0 = -1e30f, tm1 = -1e30f;
#pragma unroll
        for (int j = 0; j < 8; j++) {
            tm0 = fmaxf(tm0, fmaxf(sf[j][0], sf[j][1]));
            tm1 = fmaxf(tm1, fmaxf(sf[j][2], sf[j][3]));
        }
        tm0 = fmaxf(tm0, __shfl_xor_sync(0xffffffffu, tm0, 1));
        tm0 = fmaxf(tm0, __shfl_xor_sync(0xffffffffu, tm0, 2));
        tm1 = fmaxf(tm1, __shfl_xor_sync(0xffffffffu, tm1, 1));
        tm1 = fmaxf(tm1, __shfl_xor_sync(0xffffffffu, tm1, 2));
        float mn0 = fmaxf(m0, tm0), mn1 = fmaxf(m1, tm1);
        float c0 = fexp(m0 - mn0), c1 = fexp(m1 - mn1);
        m0 = mn0; m1 = mn1;

        float s0 = 0.f, s1 = 0.f;
        uint32_t ph[4][4], pl[4][4];
#pragma unroll
        for (int t = 0; t < 4; t++) {
            float pa = fexp(sf[2 * t][0] - mn0),     pb = fexp(sf[2 * t][1] - mn0);
            float pc = fexp(sf[2 * t][2] - mn1),     pd = fexp(sf[2 * t][3] - mn1);
            float pe = fexp(sf[2 * t + 1][0] - mn0), pf = fexp(sf[2 * t + 1][1] - mn0);
            float pg = fexp(sf[2 * t + 1][2] - mn1), pq = fexp(sf[2 * t + 1][3] - mn1);
            s0 += (pa + pb) + (pe + pf);
            s1 += (pc + pd) + (pg + pq);
            ph[t][0] = bfpack(pa, pb); pl[t][0] = bfpack(bfres(pa), bfres(pb));
            ph[t][1] = bfpack(pc, pd); pl[t][1] = bfpack(bfres(pc), bfres(pd));
            ph[t][2] = bfpack(pe, pf); pl[t][2] = bfpack(bfres(pe), bfres(pf));
            ph[t][3] = bfpack(pg, pq); pl[t][3] = bfpack(bfres(pg), bfres(pq));
        }
        s0 += __shfl_xor_sync(0xffffffffu, s0, 1);
        s0 += __shfl_xor_sync(0xffffffffu, s0, 2);
        s1 += __shfl_xor_sync(0xffffffffu, s1, 1);
        s1 += __shfl_xor_sync(0xffffffffu, s1, 2);
        l0 = l0 * c0 + s0;
        l1 = l1 * c1 + s1;
#pragma unroll
        for (int j = 0; j < 8; j++) {
            o[j][0] *= c0; o[j][1] *= c0; o[j][2] *= c1; o[j][3] *= c1;
        }

        // ---- O += P' V' ----
#pragma unroll
        for (int kc = 0; kc < 12; kc++) {
            const uint32_t* Af = (kc < 8) ? ph[kc & 3] : pl[kc & 3];
            uint32_t a4[4] = {Af[0], Af[1], Af[2], Af[3]};
#pragma unroll
            for (int jj = 0; jj < 4; jj++) {
                uint32_t r4[4];
                ldsm_x4t(r4, vbs + (kc * 16 + rv) * VSTR + (jj * 16 + cv) * 2);
                mma_bf16(o[2 * jj],     a4, r4[0], r4[1]);
                mma_bf16(o[2 * jj + 1], a4, r4[2], r4[3]);
            }
        }
        __syncthreads();   // stage s consumed; safe for next-next load
    }

    // ---- epilogue: write z split directly into g_zs ----
    float i0 = 1.f / l0, i1 = 1.f / l1;
    int b = bh >> 4, h = bh & 15;
    int srow = qb * 64 + 16 * w + (lane >> 2);
    __nv_bfloat16* z0 = g_zs + (size_t)(b * SS + srow) * KTOT;
    __nv_bfloat16* z1 = g_zs + (size_t)(b * SS + srow + 8) * KTOT;
    int kk = h * 64 + 2 * (lane & 3);
#pragma unroll
    for (int j = 0; j < 8; j++) {
        int col = kk + 8 * j;
        float v0 = o[j][0] * i0, v1 = o[j][1] * i0;
        float v2 = o[j][2] * i1, v3 = o[j][3] * i1;
        uint32_t H0 = bfpack(v0, v1), L0 = bfpack(bfres(v0), bfres(v1));
        uint32_t H1 = bfpack(v2, v3), L1 = bfpack(bfres(v2), bfres(v3));
        *(uint32_t*)(z0 + col) = H0; *(uint32_t*)(z0 + 1024 + col) = H0; *(uint32_t*)(z0 + 2048 + col) = L0;
        *(uint32_t*)(z1 + col) = H1; *(uint32_t*)(z1 + 1024 + col) = H1; *(uint32_t*)(z1 + 2048 + col) = L1;
    }
}

// ---------------------------------------------------------------------------
extern "C" void kernel_launch(void* const* d_in, const int* in_sizes, int n_in,
                              void* d_out, int out_size)
{
    const float* x  = (const float*)d_in[0];
    const float* Wq = (const float*)d_in[1];
    const float* Wk = (const float*)d_in[2];
    const float* Wv = (const float*)d_in[3];
    const float* Wo = (const float*)d_in[4];
    const float* bo = (const float*)d_in[5];
    float* out = (float*)d_out;

    cudaFuncSetAttribute(flash_mma, cudaFuncAttributeMaxDynamicSharedMemorySize, FSMEM);
    cudaFuncSetAttribute(mma_gemm<0>, cudaFuncAttributeMaxDynamicSharedMemorySize, GSMEM);
    cudaFuncSetAttribute(mma_gemm<1>, cudaFuncAttributeMaxDynamicSharedMemorySize, GSMEM);

    conv_split<<<(size_t)MM * DD / 256, 256>>>(x);
    conv_w<<<dim3(32, 32, 4), dim3(32, 8)>>>(Wq, Wk, Wv, Wo);

    mma_gemm<0><<<dim3(8, 32, 3), 256, GSMEM>>>(nullptr, nullptr);

    flash_mma<<<dim3(SS / 64, NB * NH), 128, FSMEM>>>();

    mma_gemm<1><<<dim3(8, 32, 1), 256, GSMEM>>>(bo, out);
}

// round 14
// speedup vs baseline: 1.0638x; 1.0638x over previous
#include <cuda_runtime.h>
#include <cuda_bf16.h>
#include <cstdint>

#define NB 2
#define SS 2048
#define DD 1024
#define NH 16
#define HD 64
#define MM (NB*SS)
#define KTOT 3072   // 3x K-expansion for bf16 hi/lo compensation

// ---------------------------------------------------------------------------
// Scratch (__device__ globals; allocation-free rule)
// ---------------------------------------------------------------------------
__device__ __nv_bfloat16 g_xs[(size_t)MM*KTOT];        // x split-expanded [M][3K]
__device__ __nv_bfloat16 g_zs[(size_t)MM*KTOT];        // z split-expanded [M][3K]
__device__ __nv_bfloat16 g_ws[4][(size_t)DD*KTOT];     // W transposed+split [N][3K]
__device__ __nv_bfloat16 g_qx[(size_t)NB*NH*SS*128];   // Q [bh][s][qh|ql], pre-scaled 1/8
__device__ __nv_bfloat16 g_kx[(size_t)NB*NH*SS*128];   // K [bh][s][kh|kl]
__device__ __nv_bfloat16 g_vx[(size_t)NB*NH*2*SS*HD];  // V [bh][vh rows | vl rows][hd]

// ---------------------------------------------------------------------------
// Helpers (sm_100-safe PTX: cp.async / ldmatrix / mma.sync)
// ---------------------------------------------------------------------------
__device__ __forceinline__ uint32_t smem_u32(const void* p) {
    uint32_t a;
    asm("{ .reg .u64 t; cvta.to.shared.u64 t, %1; cvt.u32.u64 %0, t; }" : "=r"(a) : "l"(p));
    return a;
}
__device__ __forceinline__ void cp16(uint32_t s, const void* g) {
    asm volatile("cp.async.cg.shared.global [%0], [%1], 16;" :: "r"(s), "l"(g));
}
__device__ __forceinline__ void ldsm_x4(uint32_t (&r)[4], uint32_t a) {
    asm volatile("ldmatrix.sync.aligned.m8n8.x4.shared.b16 {%0,%1,%2,%3}, [%4];"
                 : "=r"(r[0]), "=r"(r[1]), "=r"(r[2]), "=r"(r[3]) : "r"(a));
}
__device__ __forceinline__ void ldsm_x4t(uint32_t (&r)[4], uint32_t a) {
    asm volatile("ldmatrix.sync.aligned.m8n8.x4.trans.shared.b16 {%0,%1,%2,%3}, [%4];"
                 : "=r"(r[0]), "=r"(r[1]), "=r"(r[2]), "=r"(r[3]) : "r"(a));
}
__device__ __forceinline__ void ldsm_x2(uint32_t (&r)[2], uint32_t a) {
    asm volatile("ldmatrix.sync.aligned.m8n8.x2.shared.b16 {%0,%1}, [%2];"
                 : "=r"(r[0]), "=r"(r[1]) : "r"(a));
}
__device__ __forceinline__ void mma_bf16(float (&c)[4], const uint32_t (&a)[4],
                                         uint32_t b0, uint32_t b1) {
    asm volatile("mma.sync.aligned.m16n8k16.row.col.f32.bf16.bf16.f32 "
                 "{%0,%1,%2,%3}, {%4,%5,%6,%7}, {%8,%9}, {%0,%1,%2,%3};"
                 : "+f"(c[0]), "+f"(c[1]), "+f"(c[2]), "+f"(c[3])
                 : "r"(a[0]), "r"(a[1]), "r"(a[2]), "r"(a[3]), "r"(b0), "r"(b1));
}
__device__ __forceinline__ uint32_t bfpack(float a, float b) {
    __nv_bfloat162 t = __floats2bfloat162_rn(a, b);
    return *reinterpret_cast<uint32_t*>(&t);
}
__device__ __forceinline__ float bfres(float a) {
    return a - __bfloat162float(__float2bfloat16(a));
}
// exp on the FMA/ALU pipes (no MUFU). Valid for x <= 0; flushes to ~0 below -87.
__device__ __forceinline__ float fexp(float x) {
    float y = x * 1.4426950408889634f;
    y = fmaxf(y, -126.0f);
    float t = y + 12582912.0f;            // round-to-nearest-int (magic)
    int   i = __float_as_int(t);
    float f = y - (t - 12582912.0f);      // frac in [-0.5, 0.5]
    float p = fmaf(f, 1.3333558146e-3f, 9.6181291076e-3f);
    p = fmaf(f, p, 5.5504108664e-2f);
    p = fmaf(f, p, 2.4022650696e-1f);
    p = fmaf(f, p, 6.9314718056e-1f);
    p = fmaf(f, p, 1.0f);
    return p * __int_as_float((i + 127) << 23);
}

// ---------------------------------------------------------------------------
// Conversions
// ---------------------------------------------------------------------------
__global__ void conv_split(const float* __restrict__ xin) {
    size_t idx = (size_t)blockIdx.x * 256 + threadIdx.x;
    int m = (int)(idx >> 10), kk = (int)(idx & 1023);
    float v = xin[idx];
    __nv_bfloat16 hi = __float2bfloat16(v);
    __nv_bfloat16 lo = __float2bfloat16(v - __bfloat162float(hi));
    __nv_bfloat16* row = g_xs + (size_t)m * KTOT;
    row[kk] = hi; row[1024 + kk] = hi; row[2048 + kk] = lo;
}

// W[K,N] -> g_ws[z][N][3K]: seg0 = hi, seg1 = lo, seg2 = hi
__global__ void conv_w(const float* __restrict__ W0, const float* __restrict__ W1,
                       const float* __restrict__ W2, const float* __restrict__ W3) {
    __shared__ float t[32][33];
    const int z = blockIdx.z;
    const float* W = (z == 0) ? W0 : (z == 1) ? W1 : (z == 2) ? W2 : W3;
    __nv_bfloat16* O = g_ws[z];
    int tx = threadIdx.x, ty = threadIdx.y;
    int k0 = blockIdx.y * 32, n0 = blockIdx.x * 32;
#pragma unroll
    for (int i = 0; i < 4; i++) {
        int kk = ty * 4 + i;
        t[kk][tx] = W[(size_t)(k0 + kk) * DD + n0 + tx];
    }
    __syncthreads();
#pragma unroll
    for (int i = 0; i < 4; i++) {
        int n = n0 + ty * 4 + i;
        int k = k0 + tx;
        float v = t[tx][ty * 4 + i];
        __nv_bfloat16 hi = __float2bfloat16(v);
        __nv_bfloat16 lo = __float2bfloat16(v - __bfloat162float(hi));
        __nv_bfloat16* row = O + (size_t)n * KTOT;
        row[k] = hi; row[2048 + k] = hi; row[1024 + k] = lo;
    }
}

// ---------------------------------------------------------------------------
// mma.sync bf16 GEMM: C[4096,1024] over K=3072. 128x128 CTA, 8 warps.
// K-chunk 64, 2-stage cp.async pipeline. minctas=2 caps regs at 128.
// MODE 0: A=g_xs, B=g_ws[z]; epilogue splits into g_qx/g_kx/g_vx (bf16 hi/lo)
// MODE 1: A=g_zs, B=g_ws[3]; epilogue = Cout + bias (fp32)
// ---------------------------------------------------------------------------
#define GBK 64
#define NCH (KTOT / GBK)        // 48
#define GPAD 72                 // elements per smem row (144 B)
#define GSTG (128 * GPAD * 2)   // bytes per stage per matrix = 18432
#define GSMEM (4 * GSTG)        // 73728

template<int MODE>
__global__ __launch_bounds__(256, 2)
void mma_gemm(const float* __restrict__ bias, float* __restrict__ Cout) {
    extern __shared__ __align__(16) char gs[];
    const uint32_t sAu = smem_u32(gs);
    const uint32_t sBu = sAu + 2 * GSTG;

    const int tid = threadIdx.x;
    const int wid = tid >> 5, lane = tid & 31;
    const int wm = wid >> 2;
    const int wn = wid & 3;

    const __nv_bfloat16* A = (MODE == 0) ? g_xs : g_zs;
    const __nv_bfloat16* B = (MODE == 0) ? g_ws[blockIdx.z] : g_ws[3];
    const __nv_bfloat16* Ab = A + (size_t)blockIdx.y * 128 * KTOT;
    const __nv_bfloat16* Bb = B + (size_t)blockIdx.x * 128 * KTOT;

    const int lr = tid >> 3;            // 0..31 (+32 per t)
    const int lce = (tid & 7) * 8;      // element col
    const int lcb = lce * 2;            // byte col

    float acc[4][4][4];
#pragma unroll
    for (int i = 0; i < 4; i++)
#pragma unroll
        for (int j = 0; j < 4; j++)
#pragma unroll
            for (int v = 0; v < 4; v++) acc[i][j][v] = 0.f;

    auto load_chunk = [&](int chunk, int s) {
        const __nv_bfloat16* Ak = Ab + (size_t)chunk * GBK;
        const __nv_bfloat16* Bk = Bb + (size_t)chunk * GBK;
#pragma unroll
        for (int t = 0; t < 4; t++) {
            int row = lr + t * 32;
            cp16(sAu + s * GSTG + row * (GPAD * 2) + lcb, Ak + (size_t)row * KTOT + lce);
            cp16(sBu + s * GSTG + row * (GPAD * 2) + lcb, Bk + (size_t)row * KTOT + lce);
        }
    };

    load_chunk(0, 0);
    asm volatile("cp.async.commit_group;");

    for (int i = 0; i < NCH; i++) {
        const int s = i & 1;
        if (i + 1 < NCH) {
            load_chunk(i + 1, (i + 1) & 1);
            asm volatile("cp.async.commit_group;");
            asm volatile("cp.async.wait_group 1;");
        } else {
            asm volatile("cp.async.wait_group 0;");
        }
        __syncthreads();

#pragma unroll
        for (int k0 = 0; k0 < GBK; k0 += 16) {
            uint32_t afr[4][4];
#pragma unroll
            for (int mi = 0; mi < 4; mi++) {
                int row = wm * 64 + mi * 16 + (lane & 15);
                int col = k0 + (lane >> 4) * 8;
                ldsm_x4(afr[mi], sAu + s * GSTG + (row * GPAD + col) * 2);
            }
            uint32_t bfr[4][2];
#pragma unroll
            for (int ni = 0; ni < 4; ni++) {
                int l = lane & 15;
                int row = wn * 32 + ni * 8 + (l & 7);
                int col = k0 + (l >> 3) * 8;
                ldsm_x2(bfr[ni], sBu + s * GSTG + (row * GPAD + col) * 2);
            }
#pragma unroll
            for (int mi = 0; mi < 4; mi++)
#pragma unroll
                for (int ni = 0; ni < 4; ni++)
                    mma_bf16(acc[mi][ni], afr[mi], bfr[ni][0], bfr[ni][1]);
        }
        __syncthreads();
    }

    // Epilogue
    const int qr = lane >> 2, qc = (lane & 3) * 2;
#pragma unroll
    for (int mi = 0; mi < 4; mi++) {
#pragma unroll
        for (int ni = 0; ni < 4; ni++) {
            int col  = blockIdx.x * 128 + wn * 32 + ni * 8 + qc;
            int row0 = blockIdx.y * 128 + wm * 64 + mi * 16 + qr;
            int row1 = row0 + 8;
            float v0 = acc[mi][ni][0], v1 = acc[mi][ni][1];
            float v2 = acc[mi][ni][2], v3 = acc[mi][ni][3];
            if (MODE == 0) {
                const int z = blockIdx.z;
                if (z == 0) { v0 *= 0.125f; v1 *= 0.125f; v2 *= 0.125f; v3 *= 0.125f; }
                int h = col >> 6, hd = col & 63;
                int b0 = row0 >> 11, s0 = row0 & (SS - 1);
                int b1 = row1 >> 11, s1 = row1 & (SS - 1);
                int bh0 = b0 * NH + h, bh1 = b1 * NH + h;
                uint32_t H01 = bfpack(v0, v1), L01 = bfpack(bfres(v0), bfres(v1));
                uint32_t H23 = bfpack(v2, v3), L23 = bfpack(bfres(v2), bfres(v3));
                if (z == 0) {
                    __nv_bfloat16* p0 = g_qx + ((size_t)bh0 * SS + s0) * 128 + hd;
                    __nv_bfloat16* p1 = g_qx + ((size_t)bh1 * SS + s1) * 128 + hd;
                    *(uint32_t*)p0 = H01; *(uint32_t*)(p0 + 64) = L01;
                    *(uint32_t*)p1 = H23; *(uint32_t*)(p1 + 64) = L23;
                } else if (z == 1) {
                    __nv_bfloat16* p0 = g_kx + ((size_t)bh0 * SS + s0) * 128 + hd;
                    __nv_bfloat16* p1 = g_kx + ((size_t)bh1 * SS + s1) * 128 + hd;
                    *(uint32_t*)p0 = H01; *(uint32_t*)(p0 + 64) = L01;
                    *(uint32_t*)p1 = H23; *(uint32_t*)(p1 + 64) = L23;
                } else {
                    __nv_bfloat16* p0 = g_vx + ((size_t)bh0 * 2 * SS + s0) * HD + hd;
                    __nv_bfloat16* p1 = g_vx + ((size_t)bh1 * 2 * SS + s1) * HD + hd;
                    *(uint32_t*)p0 = H01; *(uint32_t*)(p0 + SS * HD) = L01;
                    *(uint32_t*)p1 = H23; *(uint32_t*)(p1 + SS * HD) = L23;
                }
            } else {
                float bx0 = bias[col], bx1 = bias[col + 1];
                *(float2*)(Cout + (size_t)row0 * DD + col) = make_float2(v0 + bx0, v1 + bx1);
                *(float2*)(Cout + (size_t)row1 * DD + col) = make_float2(v2 + bx0, v3 + bx1);
            }
        }
    }
}

// ---------------------------------------------------------------------------
// Flash attention on mma.sync. 64 q-rows/CTA, 4 warps (warp = 16 rows).
// Compact 2-segment storage; duplicated logical chunks reuse register frags:
//   QK: lk0-3 qh*kh, lk4-7 qh*kl, lk8-11 ql*kh   (kh frags reused)
//   PV: kc0-3 ph*vh, kc4-7 ph*vl, kc8-11 pl*vh   (vh frags reused)
// Single-stage K/V (pipelining measured neutral); 3 CTAs/SM via launch_bounds.
// smem: Q[64][272B] + K[64][272B] + V[128][144B] = 53248 B.
// ---------------------------------------------------------------------------
#define QKSTR 272          // bytes per Q/K smem row (128 bf16 + pad)
#define VSTR 144           // bytes per V smem row
#define QTB 17408          // Q tile bytes
#define KTB 17408
#define VTB 18432
#define FSMEM (QTB + KTB + VTB)   // 53248

__global__ __launch_bounds__(128, 3)
void flash_mma() {
    extern __shared__ __align__(16) char fs[];
    const uint32_t qbuf = smem_u32(fs);
    const uint32_t kbuf = qbuf + QTB;
    const uint32_t vbuf = kbuf + KTB;
    const int tid = threadIdx.x, w = tid >> 5, lane = tid & 31;
    const int qb = gridDim.x - 1 - blockIdx.x;    // heavy CTAs first
    const int bh = blockIdx.y;

    const __nv_bfloat16* Qg = g_qx + ((size_t)bh * SS + qb * 64) * 128;
    const __nv_bfloat16* Kg = g_kx + (size_t)bh * SS * 128;
    const __nv_bfloat16* Vg = g_vx + (size_t)bh * 2 * SS * HD;

    // ldmatrix per-lane offsets
    const int ra = lane & 15, ca = (lane >> 4) << 3;               // A (rows of Q)
    const int rb = (lane & 7) + ((lane >> 1) & 8), cb = lane & 8;  // B for QK (rows of K)
    const int rv = lane & 15, cv = (lane >> 4) << 3;               // B for PV (trans)

    // ---- Q into qbuf, extract 8 phys a-frags ----
#pragma unroll
    for (int t = 0; t < 8; t++) {
        int idx = tid + t * 128;                 // 0..1023; 16 chunks/row
        int r = idx >> 4, c = idx & 15;
        cp16(qbuf + r * QKSTR + c * 16, Qg + (size_t)r * 128 + c * 8);
    }
    asm volatile("cp.async.commit_group;");
    asm volatile("cp.async.wait_group 0;");
    __syncthreads();
    uint32_t qfr[8][4];
#pragma unroll
    for (int k = 0; k < 8; k++)
        ldsm_x4(qfr[k], qbuf + (16 * w + ra) * QKSTR + (k * 16 + ca) * 2);

    float m0 = -1e30f, m1 = -1e30f, l0 = 0.f, l1 = 0.f;
    float o[8][4];
#pragma unroll
    for (int j = 0; j < 8; j++)
#pragma unroll
        for (int v = 0; v < 4; v++) o[j][v] = 0.f;

    for (int kt = 0; kt <= qb; kt++) {
        // ---- load K (64x128) and V (128x64) for this tile ----
#pragma unroll
        for (int t = 0; t < 8; t++) {
            int idx = tid + t * 128;
            int r = idx >> 4, c = idx & 15;
            cp16(kbuf + r * QKSTR + c * 16, Kg + (size_t)(kt * 64 + r) * 128 + c * 8);
        }
#pragma unroll
        for (int t = 0; t < 8; t++) {
            int idx = tid + t * 128;
            int r = idx >> 3, c = idx & 7;       // r in 0..127
            int grow = (r >> 6) * SS + kt * 64 + (r & 63);
            cp16(vbuf + r * VSTR + c * 16, Vg + (size_t)grow * HD + c * 8);
        }
        asm volatile("cp.async.commit_group;");
        asm volatile("cp.async.wait_group 0;");
        __syncthreads();

        // ---- S = Q K'^T (12 logical chunks, 8 phys; kh frags reused) ----
        float sf[8][4];
#pragma unroll
        for (int j = 0; j < 8; j++)
#pragma unroll
            for (int v = 0; v < 4; v++) sf[j][v] = 0.f;
#pragma unroll
        for (int jj = 0; jj < 4; jj++) {
            uint32_t kf[4][4];
#pragma unroll
            for (int t = 0; t < 4; t++)
                ldsm_x4(kf[t], kbuf + (16 * jj + rb) * QKSTR + (t * 16 + cb) * 2);
#pragma unroll
            for (int lk = 0; lk < 4; lk++) {      // qh * kh
                mma_bf16(sf[2 * jj],     qfr[lk], kf[lk][0], kf[lk][1]);
                mma_bf16(sf[2 * jj + 1], qfr[lk], kf[lk][2], kf[lk][3]);
            }
#pragma unroll
            for (int lk = 4; lk < 8; lk++) {      // qh * kl
                uint32_t r4[4];
                ldsm_x4(r4, kbuf + (16 * jj + rb) * QKSTR + (lk * 16 + cb) * 2);
                mma_bf16(sf[2 * jj],     qfr[lk - 4], r4[0], r4[1]);
                mma_bf16(sf[2 * jj + 1], qfr[lk - 4], r4[2], r4[3]);
            }
#pragma unroll
            for (int lk = 8; lk < 12; lk++) {     // ql * kh (reuse kf)
                mma_bf16(sf[2 * jj],     qfr[lk - 4], kf[lk - 8][0], kf[lk - 8][1]);
                mma_bf16(sf[2 * jj + 1], qfr[lk - 4], kf[lk - 8][2], kf[lk - 8][3]);
            }
        }

        // ---- causal mask on diagonal tile ----
        if (kt == qb) {
            int row0 = 16 * w + (lane >> 2);
#pragma unroll
            for (int j = 0; j < 8; j++) {
                int key = 8 * j + 2 * (lane & 3);
                if (key     > row0)     sf[j][0] = -1e30f;
                if (key + 1 > row0)     sf[j][1] = -1e30f;
                if (key     > row0 + 8) sf[j][2] = -1e30f;
                if (key + 1 > row0 + 8) sf[j][3] = -1e30f;
            }
        }

        // ---- online softmax ----
        float tm0 = -1e30f, tm1 = -1e30f;
#pragma unroll
        for (int j = 0; j < 8; j++) {
            tm0 = fmaxf(tm0, fmaxf(sf[j][0], sf[j][1]));
            tm1 = fmaxf(tm1, fmaxf(sf[j][2], sf[j][3]));
        }
        tm0 = fmaxf(tm0, __shfl_xor_sync(0xffffffffu, tm0, 1));
        tm0 = fmaxf(tm0, __shfl_xor_sync(0xffffffffu, tm0, 2));
        tm1 = fmaxf(tm1, __shfl_xor_sync(0xffffffffu, tm1, 1));
        tm1 = fmaxf(tm1, __shfl_xor_sync(0xffffffffu, tm1, 2));
        float mn0 = fmaxf(m0, tm0), mn1 = fmaxf(m1, tm1);
        float c0 = fexp(m0 - mn0), c1 = fexp(m1 - mn1);
        m0 = mn0; m1 = mn1;

        float s0 = 0.f, s1 = 0.f;
        uint32_t ph[4][4], pl[4][4];
#pragma unroll
        for (int t = 0; t < 4; t++) {
            float pa = fexp(sf[2 * t][0] - mn0),     pb = fexp(sf[2 * t][1] - mn0);
            float pc = fexp(sf[2 * t][2] - mn1),     pd = fexp(sf[2 * t][3] - mn1);
            float pe = fexp(sf[2 * t + 1][0] - mn0), pf = fexp(sf[2 * t + 1][1] - mn0);
            float pg = fexp(sf[2 * t + 1][2] - mn1), pq = fexp(sf[2 * t + 1][3] - mn1);
            s0 += (pa + pb) + (pe + pf);
            s1 += (pc + pd) + (pg + pq);
            ph[t][0] = bfpack(pa, pb); pl[t][0] = bfpack(bfres(pa), bfres(pb));
            ph[t][1] = bfpack(pc, pd); pl[t][1] = bfpack(bfres(pc), bfres(pd));
            ph[t][2] = bfpack(pe, pf); pl[t][2] = bfpack(bfres(pe), bfres(pf));
            ph[t][3] = bfpack(pg, pq); pl[t][3] = bfpack(bfres(pg), bfres(pq));
        }
        s0 += __shfl_xor_sync(0xffffffffu, s0, 1);
        s0 += __shfl_xor_sync(0xffffffffu, s0, 2);
        s1 += __shfl_xor_sync(0xffffffffu, s1, 1);
        s1 += __shfl_xor_sync(0xffffffffu, s1, 2);
        l0 = l0 * c0 + s0;
        l1 = l1 * c1 + s1;
#pragma unroll
        for (int j = 0; j < 8; j++) {
            o[j][0] *= c0; o[j][1] *= c0; o[j][2] *= c1; o[j][3] *= c1;
        }

        // ---- O += P' V' (12 logical chunks, 8 phys; vh frags reused) ----
#pragma unroll
        for (int jj = 0; jj < 4; jj++) {
            uint32_t vf[4][4];
#pragma unroll
            for (int t = 0; t < 4; t++)
                ldsm_x4t(vf[t], vbuf + (t * 16 + rv) * VSTR + (jj * 16 + cv) * 2);
#pragma unroll
            for (int kc = 0; kc < 4; kc++) {      // ph * vh
                mma_bf16(o[2 * jj],     ph[kc], vf[kc][0], vf[kc][1]);
                mma_bf16(o[2 * jj + 1], ph[kc], vf[kc][2], vf[kc][3]);
            }
#pragma unroll
            for (int kc = 4; kc < 8; kc++) {      // ph * vl
                uint32_t r4[4];
                ldsm_x4t(r4, vbuf + (kc * 16 + rv) * VSTR + (jj * 16 + cv) * 2);
                mma_bf16(o[2 * jj],     ph[kc - 4], r4[0], r4[1]);
                mma_bf16(o[2 * jj + 1], ph[kc - 4], r4[2], r4[3]);
            }
#pragma unroll
            for (int kc = 8; kc < 12; kc++) {     // pl * vh (reuse vf)
                mma_bf16(o[2 * jj],     pl[kc - 8], vf[kc - 8][0], vf[kc - 8][1]);
                mma_bf16(o[2 * jj + 1], pl[kc - 8], vf[kc - 8][2], vf[kc - 8][3]);
            }
        }
        __syncthreads();   // all warps done with K/V before next overwrite
    }

    // ---- epilogue: write z split directly into g_zs ----
    float i0 = 1.f / l0, i1 = 1.f / l1;
    int b = bh >> 4, h = bh & 15;
    int srow = qb * 64 + 16 * w + (lane >> 2);
    __nv_bfloat16* z0 = g_zs + (size_t)(b * SS + srow) * KTOT;
    __nv_bfloat16* z1 = g_zs + (size_t)(b * SS + srow + 8) * KTOT;
    int kk = h * 64 + 2 * (lane & 3);
#pragma unroll
    for (int j = 0; j < 8; j++) {
        int col = kk + 8 * j;
        float v0 = o[j][0] * i0, v1 = o[j][1] * i0;
        float v2 = o[j][2] * i1, v3 = o[j][3] * i1;
        uint32_t H0 = bfpack(v0, v1), L0 = bfpack(bfres(v0), bfres(v1));
        uint32_t H1 = bfpack(v2, v3), L1 = bfpack(bfres(v2), bfres(v3));
        *(uint32_t*)(z0 + col) = H0; *(uint32_t*)(z0 + 1024 + col) = H0; *(uint32_t*)(z0 + 2048 + col) = L0;
        *(uint32_t*)(z1 + col) = H1; *(uint32_t*)(z1 + 1024 + col) = H1; *(uint32_t*)(z1 + 2048 + col) = L1;
    }
}

// ---------------------------------------------------------------------------
extern "C" void kernel_launch(void* const* d_in, const int* in_sizes, int n_in,
                              void* d_out, int out_size)
{
    const float* x  = (const float*)d_in[0];
    const float* Wq = (const float*)d_in[1];
    const float* Wk = (const float*)d_in[2];
    const float* Wv = (const float*)d_in[3];
    const float* Wo = (const float*)d_in[4];
    const float* bo = (const float*)d_in[5];
    float* out = (float*)d_out;

    cudaFuncSetAttribute(flash_mma, cudaFuncAttributeMaxDynamicSharedMemorySize, FSMEM);
    cudaFuncSetAttribute(mma_gemm<0>, cudaFuncAttributeMaxDynamicSharedMemorySize, GSMEM);
    cudaFuncSetAttribute(mma_gemm<1>, cudaFuncAttributeMaxDynamicSharedMemorySize, GSMEM);

    conv_split<<<(size_t)MM * DD / 256, 256>>>(x);
    conv_w<<<dim3(32, 32, 4), dim3(32, 8)>>>(Wq, Wk, Wv, Wo);

    mma_gemm<0><<<dim3(8, 32, 3), 256, GSMEM>>>(nullptr, nullptr);

    flash_mma<<<dim3(SS / 64, NB * NH), 128, FSMEM>>>();

    mma_gemm<1><<<dim3(8, 32, 1), 256, GSMEM>>>(bo, out);
}

// round 15
// speedup vs baseline: 1.1137x; 1.0469x over previous
#include <cuda_runtime.h>
#include <cuda_bf16.h>
#include <cstdint>

#define NB 2
#define SS 2048
#define DD 1024
#define NH 16
#define HD 64
#define MM (NB*SS)
#define KC 2048   // compact hi|lo K-expansion (products via frag reuse)

// ---------------------------------------------------------------------------
// Scratch (__device__ globals; allocation-free rule)
// ---------------------------------------------------------------------------
__device__ __nv_bfloat16 g_xs[(size_t)MM*KC];          // x [M][xh|xl]
__device__ __nv_bfloat16 g_zs[(size_t)MM*KC];          // z [M][zh|zl]
__device__ __nv_bfloat16 g_ws[4][(size_t)DD*KC];       // W^T [N][wh|wl]
__device__ __nv_bfloat16 g_qx[(size_t)NB*NH*SS*128];   // Q [bh][s][qh|ql], pre-scaled 1/8
__device__ __nv_bfloat16 g_kx[(size_t)NB*NH*SS*128];   // K [bh][s][kh|kl]
__device__ __nv_bfloat16 g_vx[(size_t)NB*NH*2*SS*HD];  // V [bh][vh rows | vl rows][hd]

// ---------------------------------------------------------------------------
// Helpers (sm_100-safe PTX: cp.async / ldmatrix / mma.sync)
// ---------------------------------------------------------------------------
__device__ __forceinline__ uint32_t smem_u32(const void* p) {
    uint32_t a;
    asm("{ .reg .u64 t; cvta.to.shared.u64 t, %1; cvt.u32.u64 %0, t; }" : "=r"(a) : "l"(p));
    return a;
}
__device__ __forceinline__ void cp16(uint32_t s, const void* g) {
    asm volatile("cp.async.cg.shared.global [%0], [%1], 16;" :: "r"(s), "l"(g));
}
__device__ __forceinline__ void ldsm_x4(uint32_t (&r)[4], uint32_t a) {
    asm volatile("ldmatrix.sync.aligned.m8n8.x4.shared.b16 {%0,%1,%2,%3}, [%4];"
                 : "=r"(r[0]), "=r"(r[1]), "=r"(r[2]), "=r"(r[3]) : "r"(a));
}
__device__ __forceinline__ void ldsm_x4t(uint32_t (&r)[4], uint32_t a) {
    asm volatile("ldmatrix.sync.aligned.m8n8.x4.trans.shared.b16 {%0,%1,%2,%3}, [%4];"
                 : "=r"(r[0]), "=r"(r[1]), "=r"(r[2]), "=r"(r[3]) : "r"(a));
}
__device__ __forceinline__ void ldsm_x2(uint32_t (&r)[2], uint32_t a) {
    asm volatile("ldmatrix.sync.aligned.m8n8.x2.shared.b16 {%0,%1}, [%2];"
                 : "=r"(r[0]), "=r"(r[1]) : "r"(a));
}
__device__ __forceinline__ void mma_bf16(float (&c)[4], const uint32_t (&a)[4],
                                         uint32_t b0, uint32_t b1) {
    asm volatile("mma.sync.aligned.m16n8k16.row.col.f32.bf16.bf16.f32 "
                 "{%0,%1,%2,%3}, {%4,%5,%6,%7}, {%8,%9}, {%0,%1,%2,%3};"
                 : "+f"(c[0]), "+f"(c[1]), "+f"(c[2]), "+f"(c[3])
                 : "r"(a[0]), "r"(a[1]), "r"(a[2]), "r"(a[3]), "r"(b0), "r"(b1));
}
__device__ __forceinline__ uint32_t bfpack(float a, float b) {
    __nv_bfloat162 t = __floats2bfloat162_rn(a, b);
    return *reinterpret_cast<uint32_t*>(&t);
}
__device__ __forceinline__ float bfres(float a) {
    return a - __bfloat162float(__float2bfloat16(a));
}
// exp on the FMA/ALU pipes (no MUFU). Valid for x <= 0; flushes to ~0 below -87.
__device__ __forceinline__ float fexp(float x) {
    float y = x * 1.4426950408889634f;
    y = fmaxf(y, -126.0f);
    float t = y + 12582912.0f;            // round-to-nearest-int (magic)
    int   i = __float_as_int(t);
    float f = y - (t - 12582912.0f);      // frac in [-0.5, 0.5]
    float p = fmaf(f, 1.3333558146e-3f, 9.6181291076e-3f);
    p = fmaf(f, p, 5.5504108664e-2f);
    p = fmaf(f, p, 2.4022650696e-1f);
    p = fmaf(f, p, 6.9314718056e-1f);
    p = fmaf(f, p, 1.0f);
    return p * __int_as_float((i + 127) << 23);
}

// ---------------------------------------------------------------------------
// Conversions (compact hi|lo)
// ---------------------------------------------------------------------------
__global__ void conv_split(const float* __restrict__ xin) {
    size_t idx = (size_t)blockIdx.x * 256 + threadIdx.x;
    int m = (int)(idx >> 10), kk = (int)(idx & 1023);
    float v = xin[idx];
    __nv_bfloat16 hi = __float2bfloat16(v);
    __nv_bfloat16 lo = __float2bfloat16(v - __bfloat162float(hi));
    __nv_bfloat16* row = g_xs + (size_t)m * KC;
    row[kk] = hi; row[1024 + kk] = lo;
}

// W[K,N] -> g_ws[z][N][wh|wl]
__global__ void conv_w(const float* __restrict__ W0, const float* __restrict__ W1,
                       const float* __restrict__ W2, const float* __restrict__ W3) {
    __shared__ float t[32][33];
    const int z = blockIdx.z;
    const float* W = (z == 0) ? W0 : (z == 1) ? W1 : (z == 2) ? W2 : W3;
    __nv_bfloat16* O = g_ws[z];
    int tx = threadIdx.x, ty = threadIdx.y;
    int k0 = blockIdx.y * 32, n0 = blockIdx.x * 32;
#pragma unroll
    for (int i = 0; i < 4; i++) {
        int kk = ty * 4 + i;
        t[kk][tx] = W[(size_t)(k0 + kk) * DD + n0 + tx];
    }
    __syncthreads();
#pragma unroll
    for (int i = 0; i < 4; i++) {
        int n = n0 + ty * 4 + i;
        int k = k0 + tx;
        float v = t[tx][ty * 4 + i];
        __nv_bfloat16 hi = __float2bfloat16(v);
        __nv_bfloat16 lo = __float2bfloat16(v - __bfloat162float(hi));
        __nv_bfloat16* row = O + (size_t)n * KC;
        row[k] = hi; row[1024 + k] = lo;
    }
}

// ---------------------------------------------------------------------------
// mma.sync bf16 GEMM with in-register compensation:
//   C = Ah*Bh + Ah*Bl + Al*Bh  over K=1024 logical, hi/lo frags reused.
// 128x128 CTA, 8 warps, K-chunk 32, 2-stage cp.async on 4 tiles (Ah/Al/Bh/Bl).
// MODE 0: A=g_xs, B=g_ws[z]; epilogue splits into g_qx/g_kx/g_vx (bf16 hi/lo)
// MODE 1: A=g_zs, B=g_ws[3]; epilogue = Cout + bias (fp32)
// ---------------------------------------------------------------------------
#define GBK 32
#define NCH (1024 / GBK)        // 32 iterations
#define TPAD 40                 // elements per tile row (80 B)
#define TSTG (128 * TPAD * 2)   // bytes per tile per stage = 10240
#define GSMEM (8 * TSTG)        // 4 tiles x 2 stages = 81920

template<int MODE>
__global__ __launch_bounds__(256, 2)
void mma_gemm(const float* __restrict__ bias, float* __restrict__ Cout) {
    extern __shared__ __align__(16) char gs[];
    const uint32_t sAh = smem_u32(gs);
    const uint32_t sAl = sAh + 2 * TSTG;
    const uint32_t sBh = sAh + 4 * TSTG;
    const uint32_t sBl = sAh + 6 * TSTG;

    const int tid = threadIdx.x;
    const int wid = tid >> 5, lane = tid & 31;
    const int wm = wid >> 2;
    const int wn = wid & 3;

    const __nv_bfloat16* A = (MODE == 0) ? g_xs : g_zs;
    const __nv_bfloat16* B = (MODE == 0) ? g_ws[blockIdx.z] : g_ws[3];
    const __nv_bfloat16* Ab = A + (size_t)blockIdx.y * 128 * KC;
    const __nv_bfloat16* Bb = B + (size_t)blockIdx.x * 128 * KC;

    // loader mapping: idx = tid + t*256 in 0..511; r = idx>>2, chunk c = idx&3
    const int lr0 = tid >> 2, lr1 = (tid + 256) >> 2;
    const int lce = (tid & 3) * 8;      // element col within 32
    const int lcb = lce * 2;            // byte col

    float acc[4][4][4];
#pragma unroll
    for (int i = 0; i < 4; i++)
#pragma unroll
        for (int j = 0; j < 4; j++)
#pragma unroll
            for (int v = 0; v < 4; v++) acc[i][j][v] = 0.f;

    auto load_chunk = [&](int chunk, int s) {
        const __nv_bfloat16* Ah = Ab + chunk * GBK;
        const __nv_bfloat16* Al = Ah + 1024;
        const __nv_bfloat16* Bh = Bb + chunk * GBK;
        const __nv_bfloat16* Bl = Bh + 1024;
        uint32_t o0 = s * TSTG + lr0 * (TPAD * 2) + lcb;
        uint32_t o1 = s * TSTG + lr1 * (TPAD * 2) + lcb;
        cp16(sAh + o0, Ah + (size_t)lr0 * KC + lce);
        cp16(sAh + o1, Ah + (size_t)lr1 * KC + lce);
        cp16(sAl + o0, Al + (size_t)lr0 * KC + lce);
        cp16(sAl + o1, Al + (size_t)lr1 * KC + lce);
        cp16(sBh + o0, Bh + (size_t)lr0 * KC + lce);
        cp16(sBh + o1, Bh + (size_t)lr1 * KC + lce);
        cp16(sBl + o0, Bl + (size_t)lr0 * KC + lce);
        cp16(sBl + o1, Bl + (size_t)lr1 * KC + lce);
    };

    load_chunk(0, 0);
    asm volatile("cp.async.commit_group;");

    for (int i = 0; i < NCH; i++) {
        const int s = i & 1;
        if (i + 1 < NCH) {
            load_chunk(i + 1, (i + 1) & 1);
            asm volatile("cp.async.commit_group;");
            asm volatile("cp.async.wait_group 1;");
        } else {
            asm volatile("cp.async.wait_group 0;");
        }
        __syncthreads();

#pragma unroll
        for (int k0 = 0; k0 < GBK; k0 += 16) {
            const uint32_t aoff = (uint32_t)(((wm * 64 + (lane & 15)) * TPAD
                                  + k0 + ((lane >> 4) << 3)) * 2) + s * TSTG;
            uint32_t ah[4][4], al[4][4];
#pragma unroll
            for (int mi = 0; mi < 4; mi++) {
                ldsm_x4(ah[mi], sAh + aoff + mi * (16 * TPAD * 2));
                ldsm_x4(al[mi], sAl + aoff + mi * (16 * TPAD * 2));
            }
            const int l = lane & 15;
            const uint32_t boff = (uint32_t)(((wn * 32 + (l & 7)) * TPAD
                                  + k0 + ((l >> 3) << 3)) * 2) + s * TSTG;
#pragma unroll
            for (int ni = 0; ni < 4; ni++) {
                uint32_t bh[2], bl[2];
                ldsm_x2(bh, sBh + boff + ni * (8 * TPAD * 2));
                ldsm_x2(bl, sBl + boff + ni * (8 * TPAD * 2));
#pragma unroll
                for (int mi = 0; mi < 4; mi++) {
                    mma_bf16(acc[mi][ni], ah[mi], bh[0], bh[1]);
                    mma_bf16(acc[mi][ni], ah[mi], bl[0], bl[1]);
                    mma_bf16(acc[mi][ni], al[mi], bh[0], bh[1]);
                }
            }
        }
        __syncthreads();
    }

    // Epilogue
    const int qr = lane >> 2, qc = (lane & 3) * 2;
#pragma unroll
    for (int mi = 0; mi < 4; mi++) {
#pragma unroll
        for (int ni = 0; ni < 4; ni++) {
            int col  = blockIdx.x * 128 + wn * 32 + ni * 8 + qc;
            int row0 = blockIdx.y * 128 + wm * 64 + mi * 16 + qr;
            int row1 = row0 + 8;
            float v0 = acc[mi][ni][0], v1 = acc[mi][ni][1];
            float v2 = acc[mi][ni][2], v3 = acc[mi][ni][3];
            if (MODE == 0) {
                const int z = blockIdx.z;
                if (z == 0) { v0 *= 0.125f; v1 *= 0.125f; v2 *= 0.125f; v3 *= 0.125f; }
                int h = col >> 6, hd = col & 63;
                int b0 = row0 >> 11, s0 = row0 & (SS - 1);
                int b1 = row1 >> 11, s1 = row1 & (SS - 1);
                int bh0 = b0 * NH + h, bh1 = b1 * NH + h;
                uint32_t H01 = bfpack(v0, v1), L01 = bfpack(bfres(v0), bfres(v1));
                uint32_t H23 = bfpack(v2, v3), L23 = bfpack(bfres(v2), bfres(v3));
                if (z == 0) {
                    __nv_bfloat16* p0 = g_qx + ((size_t)bh0 * SS + s0) * 128 + hd;
                    __nv_bfloat16* p1 = g_qx + ((size_t)bh1 * SS + s1) * 128 + hd;
                    *(uint32_t*)p0 = H01; *(uint32_t*)(p0 + 64) = L01;
                    *(uint32_t*)p1 = H23; *(uint32_t*)(p1 + 64) = L23;
                } else if (z == 1) {
                    __nv_bfloat16* p0 = g_kx + ((size_t)bh0 * SS + s0) * 128 + hd;
                    __nv_bfloat16* p1 = g_kx + ((size_t)bh1 * SS + s1) * 128 + hd;
                    *(uint32_t*)p0 = H01; *(uint32_t*)(p0 + 64) = L01;
                    *(uint32_t*)p1 = H23; *(uint32_t*)(p1 + 64) = L23;
                } else {
                    __nv_bfloat16* p0 = g_vx + ((size_t)bh0 * 2 * SS + s0) * HD + hd;
                    __nv_bfloat16* p1 = g_vx + ((size_t)bh1 * 2 * SS + s1) * HD + hd;
                    *(uint32_t*)p0 = H01; *(uint32_t*)(p0 + SS * HD) = L01;
                    *(uint32_t*)p1 = H23; *(uint32_t*)(p1 + SS * HD) = L23;
                }
            } else {
                float bx0 = bias[col], bx1 = bias[col + 1];
                *(float2*)(Cout + (size_t)row0 * DD + col) = make_float2(v0 + bx0, v1 + bx1);
                *(float2*)(Cout + (size_t)row1 * DD + col) = make_float2(v2 + bx0, v3 + bx1);
            }
        }
    }
}

// ---------------------------------------------------------------------------
// Flash attention on mma.sync (unchanged from R14 winner, epilogue compact).
// ---------------------------------------------------------------------------
#define QKSTR 272          // bytes per Q/K smem row (128 bf16 + pad)
#define VSTR 144           // bytes per V smem row
#define QTB 17408
#define KTB 17408
#define VTB 18432
#define FSMEM (QTB + KTB + VTB)   // 53248

__global__ __launch_bounds__(128, 3)
void flash_mma() {
    extern __shared__ __align__(16) char fs[];
    const uint32_t qbuf = smem_u32(fs);
    const uint32_t kbuf = qbuf + QTB;
    const uint32_t vbuf = kbuf + KTB;
    const int tid = threadIdx.x, w = tid >> 5, lane = tid & 31;
    const int qb = gridDim.x - 1 - blockIdx.x;    // heavy CTAs first
    const int bh = blockIdx.y;

    const __nv_bfloat16* Qg = g_qx + ((size_t)bh * SS + qb * 64) * 128;
    const __nv_bfloat16* Kg = g_kx + (size_t)bh * SS * 128;
    const __nv_bfloat16* Vg = g_vx + (size_t)bh * 2 * SS * HD;

    const int ra = lane & 15, ca = (lane >> 4) << 3;
    const int rb = (lane & 7) + ((lane >> 1) & 8), cb = lane & 8;
    const int rv = lane & 15, cv = (lane >> 4) << 3;

#pragma unroll
    for (int t = 0; t < 8; t++) {
        int idx = tid + t * 128;
        int r = idx >> 4, c = idx & 15;
        cp16(qbuf + r * QKSTR + c * 16, Qg + (size_t)r * 128 + c * 8);
    }
    asm volatile("cp.async.commit_group;");
    asm volatile("cp.async.wait_group 0;");
    __syncthreads();
    uint32_t qfr[8][4];
#pragma unroll
    for (int k = 0; k < 8; k++)
        ldsm_x4(qfr[k], qbuf + (16 * w + ra) * QKSTR + (k * 16 + ca) * 2);

    float m0 = -1e30f, m1 = -1e30f, l0 = 0.f, l1 = 0.f;
    float o[8][4];
#pragma unroll
    for (int j = 0; j < 8; j++)
#pragma unroll
        for (int v = 0; v < 4; v++) o[j][v] = 0.f;

    for (int kt = 0; kt <= qb; kt++) {
#pragma unroll
        for (int t = 0; t < 8; t++) {
            int idx = tid + t * 128;
            int r = idx >> 4, c = idx & 15;
            cp16(kbuf + r * QKSTR + c * 16, Kg + (size_t)(kt * 64 + r) * 128 + c * 8);
        }
#pragma unroll
        for (int t = 0; t < 8; t++) {
            int idx = tid + t * 128;
            int r = idx >> 3, c = idx & 7;
            int grow = (r >> 6) * SS + kt * 64 + (r & 63);
            cp16(vbuf + r * VSTR + c * 16, Vg + (size_t)grow * HD + c * 8);
        }
        asm volatile("cp.async.commit_group;");
        asm volatile("cp.async.wait_group 0;");
        __syncthreads();

        float sf[8][4];
#pragma unroll
        for (int j = 0; j < 8; j++)
#pragma unroll
            for (int v = 0; v < 4; v++) sf[j][v] = 0.f;
#pragma unroll
        for (int jj = 0; jj < 4; jj++) {
            uint32_t kf[4][4];
#pragma unroll
            for (int t = 0; t < 4; t++)
                ldsm_x4(kf[t], kbuf + (16 * jj + rb) * QKSTR + (t * 16 + cb) * 2);
#pragma unroll
            for (int lk = 0; lk < 4; lk++) {
                mma_bf16(sf[2 * jj],     qfr[lk], kf[lk][0], kf[lk][1]);
                mma_bf16(sf[2 * jj + 1], qfr[lk], kf[lk][2], kf[lk][3]);
            }
#pragma unroll
            for (int lk = 4; lk < 8; lk++) {
                uint32_t r4[4];
                ldsm_x4(r4, kbuf + (16 * jj + rb) * QKSTR + (lk * 16 + cb) * 2);
                mma_bf16(sf[2 * jj],     qfr[lk - 4], r4[0], r4[1]);
                mma_bf16(sf[2 * jj + 1], qfr[lk - 4], r4[2], r4[3]);
            }
#pragma unroll
            for (int lk = 8; lk < 12; lk++) {
                mma_bf16(sf[2 * jj],     qfr[lk - 4], kf[lk - 8][0], kf[lk - 8][1]);
                mma_bf16(sf[2 * jj + 1], qfr[lk - 4], kf[lk - 8][2], kf[lk - 8][3]);
            }
        }

        if (kt == qb) {
            int row0 = 16 * w + (lane >> 2);
#pragma unroll
            for (int j = 0; j < 8; j++) {
                int key = 8 * j + 2 * (lane & 3);
                if (key     > row0)     sf[j][0] = -1e30f;
                if (key + 1 > row0)     sf[j][1] = -1e30f;
                if (key     > row0 + 8) sf[j][2] = -1e30f;
                if (key + 1 > row0 + 8) sf[j][3] = -1e30f;
            }
        }

        float tm0 = -1e30f, tm1 = -1e30f;
#pragma unroll
        for (int j = 0; j < 8; j++) {
            tm0 = fmaxf(tm0, fmaxf(sf[j][0], sf[j][1]));
            tm1 = fmaxf(tm1, fmaxf(sf[j][2], sf[j][3]));
        }
        tm0 = fmaxf(tm0, __shfl_xor_sync(0xffffffffu, tm0, 1));
        tm0 = fmaxf(tm0, __shfl_xor_sync(0xffffffffu, tm0, 2));
        tm1 = fmaxf(tm1, __shfl_xor_sync(0xffffffffu, tm1, 1));
        tm1 = fmaxf(tm1, __shfl_xor_sync(0xffffffffu, tm1, 2));
        float mn0 = fmaxf(m0, tm0), mn1 = fmaxf(m1, tm1);
        float c0 = fexp(m0 - mn0), c1 = fexp(m1 - mn1);
        m0 = mn0; m1 = mn1;

        float s0 = 0.f, s1 = 0.f;
        uint32_t ph[4][4], pl[4][4];
#pragma unroll
        for (int t = 0; t < 4; t++) {
            float pa = fexp(sf[2 * t][0] - mn0),     pb = fexp(sf[2 * t][1] - mn0);
            float pc = fexp(sf[2 * t][2] - mn1),     pd = fexp(sf[2 * t][3] - mn1);
            float pe = fexp(sf[2 * t + 1][0] - mn0), pf = fexp(sf[2 * t + 1][1] - mn0);
            float pg = fexp(sf[2 * t + 1][2] - mn1), pq = fexp(sf[2 * t + 1][3] - mn1);
            s0 += (pa + pb) + (pe + pf);
            s1 += (pc + pd) + (pg + pq);
            ph[t][0] = bfpack(pa, pb); pl[t][0] = bfpack(bfres(pa), bfres(pb));
            ph[t][1] = bfpack(pc, pd); pl[t][1] = bfpack(bfres(pc), bfres(pd));
            ph[t][2] = bfpack(pe, pf); pl[t][2] = bfpack(bfres(pe), bfres(pf));
            ph[t][3] = bfpack(pg, pq); pl[t][3] = bfpack(bfres(pg), bfres(pq));
        }
        s0 += __shfl_xor_sync(0xffffffffu, s0, 1);
        s0 += __shfl_xor_sync(0xffffffffu, s0, 2);
        s1 += __shfl_xor_sync(0xffffffffu, s1, 1);
        s1 += __shfl_xor_sync(0xffffffffu, s1, 2);
        l0 = l0 * c0 + s0;
        l1 = l1 * c1 + s1;
#pragma unroll
        for (int j = 0; j < 8; j++) {
            o[j][0] *= c0; o[j][1] *= c0; o[j][2] *= c1; o[j][3] *= c1;
        }

#pragma unroll
        for (int jj = 0; jj < 4; jj++) {
            uint32_t vf[4][4];
#pragma unroll
            for (int t = 0; t < 4; t++)
                ldsm_x4t(vf[t], vbuf + (t * 16 + rv) * VSTR + (jj * 16 + cv) * 2);
#pragma unroll
            for (int kc = 0; kc < 4; kc++) {
                mma_bf16(o[2 * jj],     ph[kc], vf[kc][0], vf[kc][1]);
                mma_bf16(o[2 * jj + 1], ph[kc], vf[kc][2], vf[kc][3]);
            }
#pragma unroll
            for (int kc = 4; kc < 8; kc++) {
                uint32_t r4[4];
                ldsm_x4t(r4, vbuf + (kc * 16 + rv) * VSTR + (jj * 16 + cv) * 2);
                mma_bf16(o[2 * jj],     ph[kc - 4], r4[0], r4[1]);
                mma_bf16(o[2 * jj + 1], ph[kc - 4], r4[2], r4[3]);
            }
#pragma unroll
            for (int kc = 8; kc < 12; kc++) {
                mma_bf16(o[2 * jj],     pl[kc - 8], vf[kc - 8][0], vf[kc - 8][1]);
                mma_bf16(o[2 * jj + 1], pl[kc - 8], vf[kc - 8][2], vf[kc - 8][3]);
            }
        }
        __syncthreads();
    }

    // ---- epilogue: write z split (compact) into g_zs ----
    float i0 = 1.f / l0, i1 = 1.f / l1;
    int b = bh >> 4, h = bh & 15;
    int srow = qb * 64 + 16 * w + (lane >> 2);
    __nv_bfloat16* z0 = g_zs + (size_t)(b * SS + srow) * KC;
    __nv_bfloat16* z1 = g_zs + (size_t)(b * SS + srow + 8) * KC;
    int kk = h * 64 + 2 * (lane & 3);
#pragma unroll
    for (int j = 0; j < 8; j++) {
        int col = kk + 8 * j;
        float v0 = o[j][0] * i0, v1 = o[j][1] * i0;
        float v2 = o[j][2] * i1, v3 = o[j][3] * i1;
        uint32_t H0 = bfpack(v0, v1), L0 = bfpack(bfres(v0), bfres(v1));
        uint32_t H1 = bfpack(v2, v3), L1 = bfpack(bfres(v2), bfres(v3));
        *(uint32_t*)(z0 + col) = H0; *(uint32_t*)(z0 + 1024 + col) = L0;
        *(uint32_t*)(z1 + col) = H1; *(uint32_t*)(z1 + 1024 + col) = L1;
    }
}

// ---------------------------------------------------------------------------
extern "C" void kernel_launch(void* const* d_in, const int* in_sizes, int n_in,
                              void* d_out, int out_size)
{
    const float* x  = (const float*)d_in[0];
    const float* Wq = (const float*)d_in[1];
    const float* Wk = (const float*)d_in[2];
    const float* Wv = (const float*)d_in[3];
    const float* Wo = (const float*)d_in[4];
    const float* bo = (const float*)d_in[5];
    float* out = (float*)d_out;

    cudaFuncSetAttribute(flash_mma, cudaFuncAttributeMaxDynamicSharedMemorySize, FSMEM);
    cudaFuncSetAttribute(mma_gemm<0>, cudaFuncAttributeMaxDynamicSharedMemorySize, GSMEM);
    cudaFuncSetAttribute(mma_gemm<1>, cudaFuncAttributeMaxDynamicSharedMemorySize, GSMEM);

    conv_split<<<(size_t)MM * DD / 256, 256>>>(x);
    conv_w<<<dim3(32, 32, 4), dim3(32, 8)>>>(Wq, Wk, Wv, Wo);

    mma_gemm<0><<<dim3(8, 32, 3), 256, GSMEM>>>(nullptr, nullptr);

    flash_mma<<<dim3(SS / 64, NB * NH), 128, FSMEM>>>();

    mma_gemm<1><<<dim3(8, 32), 256, GSMEM>>>(bo, out);
}

// round 16
// speedup vs baseline: 1.1327x; 1.0170x over previous
#include <cuda_runtime.h>
#include <cuda_bf16.h>
#include <cstdint>

#define NB 2
#define SS 2048
#define DD 1024
#define NH 16
#define HD 64
#define MM (NB*SS)
#define KC 2048   // compact hi|lo K-expansion (products via frag reuse)

// ---------------------------------------------------------------------------
// Scratch (__device__ globals; allocation-free rule)
// ---------------------------------------------------------------------------
__device__ __nv_bfloat16 g_xs[(size_t)MM*KC];          // x [M][xh|xl]
__device__ __nv_bfloat16 g_zs[(size_t)MM*KC];          // z [M][zh|zl]
__device__ __nv_bfloat16 g_ws[4][(size_t)DD*KC];       // W^T [N][wh|wl]
__device__ __nv_bfloat16 g_qx[(size_t)NB*NH*SS*128];   // Q [bh][s][qh|ql], pre-scaled 1/8
__device__ __nv_bfloat16 g_kx[(size_t)NB*NH*SS*128];   // K [bh][s][kh|kl]
__device__ __nv_bfloat16 g_vx[(size_t)NB*NH*2*SS*HD];  // V [bh][vh rows | vl rows][hd]

// ---------------------------------------------------------------------------
// Helpers (sm_100-safe PTX: cp.async / ldmatrix / mma.sync)
// ---------------------------------------------------------------------------
__device__ __forceinline__ uint32_t smem_u32(const void* p) {
    uint32_t a;
    asm("{ .reg .u64 t; cvta.to.shared.u64 t, %1; cvt.u32.u64 %0, t; }" : "=r"(a) : "l"(p));
    return a;
}
__device__ __forceinline__ void cp16(uint32_t s, const void* g) {
    asm volatile("cp.async.cg.shared.global [%0], [%1], 16;" :: "r"(s), "l"(g));
}
__device__ __forceinline__ void ldsm_x4(uint32_t (&r)[4], uint32_t a) {
    asm volatile("ldmatrix.sync.aligned.m8n8.x4.shared.b16 {%0,%1,%2,%3}, [%4];"
                 : "=r"(r[0]), "=r"(r[1]), "=r"(r[2]), "=r"(r[3]) : "r"(a));
}
__device__ __forceinline__ void ldsm_x4t(uint32_t (&r)[4], uint32_t a) {
    asm volatile("ldmatrix.sync.aligned.m8n8.x4.trans.shared.b16 {%0,%1,%2,%3}, [%4];"
                 : "=r"(r[0]), "=r"(r[1]), "=r"(r[2]), "=r"(r[3]) : "r"(a));
}
__device__ __forceinline__ void mma_bf16(float (&c)[4], const uint32_t (&a)[4],
                                         uint32_t b0, uint32_t b1) {
    asm volatile("mma.sync.aligned.m16n8k16.row.col.f32.bf16.bf16.f32 "
                 "{%0,%1,%2,%3}, {%4,%5,%6,%7}, {%8,%9}, {%0,%1,%2,%3};"
                 : "+f"(c[0]), "+f"(c[1]), "+f"(c[2]), "+f"(c[3])
                 : "r"(a[0]), "r"(a[1]), "r"(a[2]), "r"(a[3]), "r"(b0), "r"(b1));
}
__device__ __forceinline__ uint32_t bfpack(float a, float b) {
    __nv_bfloat162 t = __floats2bfloat162_rn(a, b);
    return *reinterpret_cast<uint32_t*>(&t);
}
__device__ __forceinline__ float bfres(float a) {
    return a - __bfloat162float(__float2bfloat16(a));
}
// exp on the FMA/ALU pipes (no MUFU). Valid for x <= 0; flushes to ~0 below -87.
__device__ __forceinline__ float fexp(float x) {
    float y = x * 1.4426950408889634f;
    y = fmaxf(y, -126.0f);
    float t = y + 12582912.0f;            // round-to-nearest-int (magic)
    int   i = __float_as_int(t);
    float f = y - (t - 12582912.0f);      // frac in [-0.5, 0.5]
    float p = fmaf(f, 9.6181291076e-3f, 5.5504108664e-2f);
    p = fmaf(f, p, 2.4022650696e-1f);
    p = fmaf(f, p, 6.9314718056e-1f);
    p = fmaf(f, p, 1.0f);
    return p * __int_as_float((i + 127) << 23);
}

// ---------------------------------------------------------------------------
// Conversions (compact hi|lo)
// ---------------------------------------------------------------------------
__global__ void conv_split(const float* __restrict__ xin) {
    size_t idx = (size_t)blockIdx.x * 256 + threadIdx.x;
    int m = (int)(idx >> 10), kk = (int)(idx & 1023);
    float v = xin[idx];
    __nv_bfloat16 hi = __float2bfloat16(v);
    __nv_bfloat16 lo = __float2bfloat16(v - __bfloat162float(hi));
    __nv_bfloat16* row = g_xs + (size_t)m * KC;
    row[kk] = hi; row[1024 + kk] = lo;
}

// W[K,N] -> g_ws[z][N][wh|wl]
__global__ void conv_w(const float* __restrict__ W0, const float* __restrict__ W1,
                       const float* __restrict__ W2, const float* __restrict__ W3) {
    __shared__ float t[32][33];
    const int z = blockIdx.z;
    const float* W = (z == 0) ? W0 : (z == 1) ? W1 : (z == 2) ? W2 : W3;
    __nv_bfloat16* O = g_ws[z];
    int tx = threadIdx.x, ty = threadIdx.y;
    int k0 = blockIdx.y * 32, n0 = blockIdx.x * 32;
#pragma unroll
    for (int i = 0; i < 4; i++) {
        int kk = ty * 4 + i;
        t[kk][tx] = W[(size_t)(k0 + kk) * DD + n0 + tx];
    }
    __syncthreads();
#pragma unroll
    for (int i = 0; i < 4; i++) {
        int n = n0 + ty * 4 + i;
        int k = k0 + tx;
        float v = t[tx][ty * 4 + i];
        __nv_bfloat16 hi = __float2bfloat16(v);
        __nv_bfloat16 lo = __float2bfloat16(v - __bfloat162float(hi));
        __nv_bfloat16* row = O + (size_t)n * KC;
        row[k] = hi; row[1024 + k] = lo;
    }
}

// ---------------------------------------------------------------------------
// mma.sync bf16 GEMM with in-register compensation:
//   C = Ah*Bh + Ah*Bl + Al*Bh  over K=1024 logical, hi/lo frags reused.
// 128x128 CTA, 8 warps, K-chunk 32, 2-stage cp.async on 4 tiles (Ah/Al/Bh/Bl).
// B frags via ldmatrix.x4 (two ni-pairs per load).
// MODE 0: A=g_xs, B=g_ws[z]; epilogue splits into g_qx/g_kx/g_vx (bf16 hi/lo)
// MODE 1: A=g_zs, B=g_ws[3]; epilogue = Cout + bias (fp32)
// ---------------------------------------------------------------------------
#define GBK 32
#define NCH (1024 / GBK)        // 32 iterations
#define TPAD 40                 // elements per tile row (80 B)
#define TSTG (128 * TPAD * 2)   // bytes per tile per stage = 10240
#define GSMEM (8 * TSTG)        // 4 tiles x 2 stages = 81920

template<int MODE>
__global__ __launch_bounds__(256, 2)
void mma_gemm(const float* __restrict__ bias, float* __restrict__ Cout) {
    extern __shared__ __align__(16) char gs[];
    const uint32_t sAh = smem_u32(gs);
    const uint32_t sAl = sAh + 2 * TSTG;
    const uint32_t sBh = sAh + 4 * TSTG;
    const uint32_t sBl = sAh + 6 * TSTG;

    const int tid = threadIdx.x;
    const int wid = tid >> 5, lane = tid & 31;
    const int wm = wid >> 2;
    const int wn = wid & 3;

    const __nv_bfloat16* A = (MODE == 0) ? g_xs : g_zs;
    const __nv_bfloat16* B = (MODE == 0) ? g_ws[blockIdx.z] : g_ws[3];
    const __nv_bfloat16* Ab = A + (size_t)blockIdx.y * 128 * KC;
    const __nv_bfloat16* Bb = B + (size_t)blockIdx.x * 128 * KC;

    const int lr0 = tid >> 2, lr1 = (tid + 256) >> 2;
    const int lce = (tid & 3) * 8;
    const int lcb = lce * 2;

    // ldmatrix lane maps (A: x4 over 16 rows x 16 cols; B: x4 over 16 rows x 16 cols)
    const int ra = lane & 15, ca = (lane >> 4) << 3;
    const int rb2 = (lane & 7) + ((lane >> 1) & 8), cb2 = lane & 8;

    float acc[4][4][4];
#pragma unroll
    for (int i = 0; i < 4; i++)
#pragma unroll
        for (int j = 0; j < 4; j++)
#pragma unroll
            for (int v = 0; v < 4; v++) acc[i][j][v] = 0.f;

    auto load_chunk = [&](int chunk, int s) {
        const __nv_bfloat16* Ah = Ab + chunk * GBK;
        const __nv_bfloat16* Al = Ah + 1024;
        const __nv_bfloat16* Bh = Bb + chunk * GBK;
        const __nv_bfloat16* Bl = Bh + 1024;
        uint32_t o0 = s * TSTG + lr0 * (TPAD * 2) + lcb;
        uint32_t o1 = s * TSTG + lr1 * (TPAD * 2) + lcb;
        cp16(sAh + o0, Ah + (size_t)lr0 * KC + lce);
        cp16(sAh + o1, Ah + (size_t)lr1 * KC + lce);
        cp16(sAl + o0, Al + (size_t)lr0 * KC + lce);
        cp16(sAl + o1, Al + (size_t)lr1 * KC + lce);
        cp16(sBh + o0, Bh + (size_t)lr0 * KC + lce);
        cp16(sBh + o1, Bh + (size_t)lr1 * KC + lce);
        cp16(sBl + o0, Bl + (size_t)lr0 * KC + lce);
        cp16(sBl + o1, Bl + (size_t)lr1 * KC + lce);
    };

    load_chunk(0, 0);
    asm volatile("cp.async.commit_group;");

    for (int i = 0; i < NCH; i++) {
        const int s = i & 1;
        if (i + 1 < NCH) {
            load_chunk(i + 1, (i + 1) & 1);
            asm volatile("cp.async.commit_group;");
            asm volatile("cp.async.wait_group 1;");
        } else {
            asm volatile("cp.async.wait_group 0;");
        }
        __syncthreads();

#pragma unroll
        for (int k0 = 0; k0 < GBK; k0 += 16) {
            const uint32_t aoff = (uint32_t)(((wm * 64 + ra) * TPAD + k0 + ca) * 2) + s * TSTG;
            uint32_t ah[4][4], al[4][4];
#pragma unroll
            for (int mi = 0; mi < 4; mi++) {
                ldsm_x4(ah[mi], sAh + aoff + mi * (16 * TPAD * 2));
                ldsm_x4(al[mi], sAl + aoff + mi * (16 * TPAD * 2));
            }
            const uint32_t boff = (uint32_t)(((wn * 32 + rb2) * TPAD + k0 + cb2) * 2) + s * TSTG;
#pragma unroll
            for (int pp = 0; pp < 2; pp++) {
                uint32_t bh4[4], bl4[4];
                ldsm_x4(bh4, sBh + boff + pp * (16 * TPAD * 2));
                ldsm_x4(bl4, sBl + boff + pp * (16 * TPAD * 2));
#pragma unroll
                for (int mi = 0; mi < 4; mi++) {
                    mma_bf16(acc[mi][2 * pp], ah[mi], bh4[0], bh4[1]);
                    mma_bf16(acc[mi][2 * pp], ah[mi], bl4[0], bl4[1]);
                    mma_bf16(acc[mi][2 * pp], al[mi], bh4[0], bh4[1]);
                    mma_bf16(acc[mi][2 * pp + 1], ah[mi], bh4[2], bh4[3]);
                    mma_bf16(acc[mi][2 * pp + 1], ah[mi], bl4[2], bl4[3]);
                    mma_bf16(acc[mi][2 * pp + 1], al[mi], bh4[2], bh4[3]);
                }
            }
        }
        __syncthreads();
    }

    // Epilogue
    const int qr = lane >> 2, qc = (lane & 3) * 2;
#pragma unroll
    for (int mi = 0; mi < 4; mi++) {
#pragma unroll
        for (int ni = 0; ni < 4; ni++) {
            int col  = blockIdx.x * 128 + wn * 32 + ni * 8 + qc;
            int row0 = blockIdx.y * 128 + wm * 64 + mi * 16 + qr;
            int row1 = row0 + 8;
            float v0 = acc[mi][ni][0], v1 = acc[mi][ni][1];
            float v2 = acc[mi][ni][2], v3 = acc[mi][ni][3];
            if (MODE == 0) {
                const int z = blockIdx.z;
                if (z == 0) { v0 *= 0.125f; v1 *= 0.125f; v2 *= 0.125f; v3 *= 0.125f; }
                int h = col >> 6, hd = col & 63;
                int b0 = row0 >> 11, s0 = row0 & (SS - 1);
                int b1 = row1 >> 11, s1 = row1 & (SS - 1);
                int bh0 = b0 * NH + h, bh1 = b1 * NH + h;
                uint32_t H01 = bfpack(v0, v1), L01 = bfpack(bfres(v0), bfres(v1));
                uint32_t H23 = bfpack(v2, v3), L23 = bfpack(bfres(v2), bfres(v3));
                if (z == 0) {
                    __nv_bfloat16* p0 = g_qx + ((size_t)bh0 * SS + s0) * 128 + hd;
                    __nv_bfloat16* p1 = g_qx + ((size_t)bh1 * SS + s1) * 128 + hd;
                    *(uint32_t*)p0 = H01; *(uint32_t*)(p0 + 64) = L01;
                    *(uint32_t*)p1 = H23; *(uint32_t*)(p1 + 64) = L23;
                } else if (z == 1) {
                    __nv_bfloat16* p0 = g_kx + ((size_t)bh0 * SS + s0) * 128 + hd;
                    __nv_bfloat16* p1 = g_kx + ((size_t)bh1 * SS + s1) * 128 + hd;
                    *(uint32_t*)p0 = H01; *(uint32_t*)(p0 + 64) = L01;
                    *(uint32_t*)p1 = H23; *(uint32_t*)(p1 + 64) = L23;
                } else {
                    __nv_bfloat16* p0 = g_vx + ((size_t)bh0 * 2 * SS + s0) * HD + hd;
                    __nv_bfloat16* p1 = g_vx + ((size_t)bh1 * 2 * SS + s1) * HD + hd;
                    *(uint32_t*)p0 = H01; *(uint32_t*)(p0 + SS * HD) = L01;
                    *(uint32_t*)p1 = H23; *(uint32_t*)(p1 + SS * HD) = L23;
                }
            } else {
                float bx0 = bias[col], bx1 = bias[col + 1];
                *(float2*)(Cout + (size_t)row0 * DD + col) = make_float2(v0 + bx0, v1 + bx1);
                *(float2*)(Cout + (size_t)row1 * DD + col) = make_float2(v2 + bx0, v3 + bx1);
            }
        }
    }
}

// ---------------------------------------------------------------------------
// Flash attention on mma.sync. 64 q-rows/CTA, 4 warps. Deferred l-reduction
// (per-lane partials; single shuffle-reduce in epilogue).
// ---------------------------------------------------------------------------
#define QKSTR 272          // bytes per Q/K smem row (128 bf16 + pad)
#define VSTR 144           // bytes per V smem row
#define QTB 17408
#define KTB 17408
#define VTB 18432
#define FSMEM (QTB + KTB + VTB)   // 53248

__global__ __launch_bounds__(128, 3)
void flash_mma() {
    extern __shared__ __align__(16) char fs[];
    const uint32_t qbuf = smem_u32(fs);
    const uint32_t kbuf = qbuf + QTB;
    const uint32_t vbuf = kbuf + KTB;
    const int tid = threadIdx.x, w = tid >> 5, lane = tid & 31;
    const int qb = gridDim.x - 1 - blockIdx.x;    // heavy CTAs first
    const int bh = blockIdx.y;

    const __nv_bfloat16* Qg = g_qx + ((size_t)bh * SS + qb * 64) * 128;
    const __nv_bfloat16* Kg = g_kx + (size_t)bh * SS * 128;
    const __nv_bfloat16* Vg = g_vx + (size_t)bh * 2 * SS * HD;

    const int ra = lane & 15, ca = (lane >> 4) << 3;
    const int rb = (lane & 7) + ((lane >> 1) & 8), cb = lane & 8;
    const int rv = lane & 15, cv = (lane >> 4) << 3;

#pragma unroll
    for (int t = 0; t < 8; t++) {
        int idx = tid + t * 128;
        int r = idx >> 4, c = idx & 15;
        cp16(qbuf + r * QKSTR + c * 16, Qg + (size_t)r * 128 + c * 8);
    }
    asm volatile("cp.async.commit_group;");
    asm volatile("cp.async.wait_group 0;");
    __syncthreads();
    uint32_t qfr[8][4];
#pragma unroll
    for (int k = 0; k < 8; k++)
        ldsm_x4(qfr[k], qbuf + (16 * w + ra) * QKSTR + (k * 16 + ca) * 2);

    float m0 = -1e30f, m1 = -1e30f, l0 = 0.f, l1 = 0.f;   // l = per-lane partials
    float o[8][4];
#pragma unroll
    for (int j = 0; j < 8; j++)
#pragma unroll
        for (int v = 0; v < 4; v++) o[j][v] = 0.f;

    for (int kt = 0; kt <= qb; kt++) {
#pragma unroll
        for (int t = 0; t < 8; t++) {
            int idx = tid + t * 128;
            int r = idx >> 4, c = idx & 15;
            cp16(kbuf + r * QKSTR + c * 16, Kg + (size_t)(kt * 64 + r) * 128 + c * 8);
        }
#pragma unroll
        for (int t = 0; t < 8; t++) {
            int idx = tid + t * 128;
            int r = idx >> 3, c = idx & 7;
            int grow = (r >> 6) * SS + kt * 64 + (r & 63);
            cp16(vbuf + r * VSTR + c * 16, Vg + (size_t)grow * HD + c * 8);
        }
        asm volatile("cp.async.commit_group;");
        asm volatile("cp.async.wait_group 0;");
        __syncthreads();

        float sf[8][4];
#pragma unroll
        for (int j = 0; j < 8; j++)
#pragma unroll
            for (int v = 0; v < 4; v++) sf[j][v] = 0.f;
#pragma unroll
        for (int jj = 0; jj < 4; jj++) {
            uint32_t kf[4][4];
#pragma unroll
            for (int t = 0; t < 4; t++)
                ldsm_x4(kf[t], kbuf + (16 * jj + rb) * QKSTR + (t * 16 + cb) * 2);
#pragma unroll
            for (int lk = 0; lk < 4; lk++) {
                mma_bf16(sf[2 * jj],     qfr[lk], kf[lk][0], kf[lk][1]);
                mma_bf16(sf[2 * jj + 1], qfr[lk], kf[lk][2], kf[lk][3]);
            }
#pragma unroll
            for (int lk = 4; lk < 8; lk++) {
                uint32_t r4[4];
                ldsm_x4(r4, kbuf + (16 * jj + rb) * QKSTR + (lk * 16 + cb) * 2);
                mma_bf16(sf[2 * jj],     qfr[lk - 4], r4[0], r4[1]);
                mma_bf16(sf[2 * jj + 1], qfr[lk - 4], r4[2], r4[3]);
            }
#pragma unroll
            for (int lk = 8; lk < 12; lk++) {
                mma_bf16(sf[2 * jj],     qfr[lk - 4], kf[lk - 8][0], kf[lk - 8][1]);
                mma_bf16(sf[2 * jj + 1], qfr[lk - 4], kf[lk - 8][2], kf[lk - 8][3]);
            }
        }

        if (kt == qb) {
            int row0 = 16 * w + (lane >> 2);
#pragma unroll
            for (int j = 0; j < 8; j++) {
                int key = 8 * j + 2 * (lane & 3);
                if (key     > row0)     sf[j][0] = -1e30f;
                if (key + 1 > row0)     sf[j][1] = -1e30f;
                if (key     > row0 + 8) sf[j][2] = -1e30f;
                if (key + 1 > row0 + 8) sf[j][3] = -1e30f;
            }
        }

        float tm0 = -1e30f, tm1 = -1e30f;
#pragma unroll
        for (int j = 0; j < 8; j++) {
            tm0 = fmaxf(tm0, fmaxf(sf[j][0], sf[j][1]));
            tm1 = fmaxf(tm1, fmaxf(sf[j][2], sf[j][3]));
        }
        tm0 = fmaxf(tm0, __shfl_xor_sync(0xffffffffu, tm0, 1));
        tm0 = fmaxf(tm0, __shfl_xor_sync(0xffffffffu, tm0, 2));
        tm1 = fmaxf(tm1, __shfl_xor_sync(0xffffffffu, tm1, 1));
        tm1 = fmaxf(tm1, __shfl_xor_sync(0xffffffffu, tm1, 2));
        float mn0 = fmaxf(m0, tm0), mn1 = fmaxf(m1, tm1);
        float c0 = fexp(m0 - mn0), c1 = fexp(m1 - mn1);
        m0 = mn0; m1 = mn1;

        float s0 = 0.f, s1 = 0.f;
        uint32_t ph[4][4], pl[4][4];
#pragma unroll
        for (int t = 0; t < 4; t++) {
            float pa = fexp(sf[2 * t][0] - mn0),     pb = fexp(sf[2 * t][1] - mn0);
            float pc = fexp(sf[2 * t][2] - mn1),     pd = fexp(sf[2 * t][3] - mn1);
            float pe = fexp(sf[2 * t + 1][0] - mn0), pf = fexp(sf[2 * t + 1][1] - mn0);
            float pg = fexp(sf[2 * t + 1][2] - mn1), pq = fexp(sf[2 * t + 1][3] - mn1);
            s0 += (pa + pb) + (pe + pf);
            s1 += (pc + pd) + (pg + pq);
            ph[t][0] = bfpack(pa, pb); pl[t][0] = bfpack(bfres(pa), bfres(pb));
            ph[t][1] = bfpack(pc, pd); pl[t][1] = bfpack(bfres(pc), bfres(pd));
            ph[t][2] = bfpack(pe, pf); pl[t][2] = bfpack(bfres(pe), bfres(pf));
            ph[t][3] = bfpack(pg, pq); pl[t][3] = bfpack(bfres(pg), bfres(pq));
        }
        // deferred: per-lane partial update, no shuffles here
        l0 = l0 * c0 + s0;
        l1 = l1 * c1 + s1;
#pragma unroll
        for (int j = 0; j < 8; j++) {
            o[j][0] *= c0; o[j][1] *= c0; o[j][2] *= c1; o[j][3] *= c1;
        }

#pragma unroll
        for (int jj = 0; jj < 4; jj++) {
            uint32_t vf[4][4];
#pragma unroll
            for (int t = 0; t < 4; t++)
                ldsm_x4t(vf[t], vbuf + (t * 16 + rv) * VSTR + (jj * 16 + cv) * 2);
#pragma unroll
            for (int kc = 0; kc < 4; kc++) {
                mma_bf16(o[2 * jj],     ph[kc], vf[kc][0], vf[kc][1]);
                mma_bf16(o[2 * jj + 1], ph[kc], vf[kc][2], vf[kc][3]);
            }
#pragma unroll
            for (int kc = 4; kc < 8; kc++) {
                uint32_t r4[4];
                ldsm_x4t(r4, vbuf + (kc * 16 + rv) * VSTR + (jj * 16 + cv) * 2);
                mma_bf16(o[2 * jj],     ph[kc - 4], r4[0], r4[1]);
                mma_bf16(o[2 * jj + 1], ph[kc - 4], r4[2], r4[3]);
            }
#pragma unroll
            for (int kc = 8; kc < 12; kc++) {
                mma_bf16(o[2 * jj],     pl[kc - 8], vf[kc - 8][0], vf[kc - 8][1]);
                mma_bf16(o[2 * jj + 1], pl[kc - 8], vf[kc - 8][2], vf[kc - 8][3]);
            }
        }
        __syncthreads();
    }

    // ---- final l reduction (deferred shuffles) ----
    l0 += __shfl_xor_sync(0xffffffffu, l0, 1);
    l0 += __shfl_xor_sync(0xffffffffu, l0, 2);
    l1 += __shfl_xor_sync(0xffffffffu, l1, 1);
    l1 += __shfl_xor_sync(0xffffffffu, l1, 2);

    // ---- epilogue: write z split (compact) into g_zs ----
    float i0 = 1.f / l0, i1 = 1.f / l1;
    int b = bh >> 4, h = bh & 15;
    int srow = qb * 64 + 16 * w + (lane >> 2);
    __nv_bfloat16* z0 = g_zs + (size_t)(b * SS + srow) * KC;
    __nv_bfloat16* z1 = g_zs + (size_t)(b * SS + srow + 8) * KC;
    int kk = h * 64 + 2 * (lane & 3);
#pragma unroll
    for (int j = 0; j < 8; j++) {
        int col = kk + 8 * j;
        float v0 = o[j][0] * i0, v1 = o[j][1] * i0;
        float v2 = o[j][2] * i1, v3 = o[j][3] * i1;
        uint32_t H0 = bfpack(v0, v1), L0 = bfpack(bfres(v0), bfres(v1));
        uint32_t H1 = bfpack(v2, v3), L1 = bfpack(bfres(v2), bfres(v3));
        *(uint32_t*)(z0 + col) = H0; *(uint32_t*)(z0 + 1024 + col) = L0;
        *(uint32_t*)(z1 + col) = H1; *(uint32_t*)(z1 + 1024 + col) = L1;
    }
}

// ---------------------------------------------------------------------------
extern "C" void kernel_launch(void* const* d_in, const int* in_sizes, int n_in,
                              void* d_out, int out_size)
{
    const float* x  = (const float*)d_in[0];
    const float* Wq = (const float*)d_in[1];
    const float* Wk = (const float*)d_in[2];
    const float* Wv = (const float*)d_in[3];
    const float* Wo = (const float*)d_in[4];
    const float* bo = (const float*)d_in[5];
    float* out = (float*)d_out;

    cudaFuncSetAttribute(flash_mma, cudaFuncAttributeMaxDynamicSharedMemorySize, FSMEM);
    cudaFuncSetAttribute(mma_gemm<0>, cudaFuncAttributeMaxDynamicSharedMemorySize, GSMEM);
    cudaFuncSetAttribute(mma_gemm<1>, cudaFuncAttributeMaxDynamicSharedMemorySize, GSMEM);

    conv_split<<<(size_t)MM * DD / 256, 256>>>(x);
    conv_w<<<dim3(32, 32, 4), dim3(32, 8)>>>(Wq, Wk, Wv, Wo);

    mma_gemm<0><<<dim3(8, 32, 3), 256, GSMEM>>>(nullptr, nullptr);

    flash_mma<<<dim3(SS / 64, NB * NH), 128, FSMEM>>>();

    mma_gemm<1><<<dim3(8, 32), 256, GSMEM>>>(bo, out);
}

// round 17
// speedup vs baseline: 1.1327x; 1.0001x over previous
#include <cuda_runtime.h>
#include <cuda_bf16.h>
#include <cstdint>

#define NB 2
#define SS 2048
#define DD 1024
#define NH 16
#define HD 64
#define MM (NB*SS)
#define KC 2048   // compact hi|lo K-expansion (products via frag reuse)

// ---------------------------------------------------------------------------
// Scratch (__device__ globals; allocation-free rule)
// ---------------------------------------------------------------------------
__device__ __nv_bfloat16 g_xs[(size_t)MM*KC];          // x [M][xh|xl]
__device__ __nv_bfloat16 g_zs[(size_t)MM*KC];          // z [M][zh|zl]
__device__ __nv_bfloat16 g_ws[4][(size_t)DD*KC];       // W^T [N][wh|wl]
__device__ __nv_bfloat16 g_qx[(size_t)NB*NH*SS*128];   // Q [bh][s][qh|ql], pre-scaled 1/8
__device__ __nv_bfloat16 g_kx[(size_t)NB*NH*SS*128];   // K [bh][s][kh|kl]
__device__ __nv_bfloat16 g_vx[(size_t)NB*NH*2*SS*HD];  // V [bh][vh rows | vl rows][hd]

// ---------------------------------------------------------------------------
// Helpers (sm_100-safe PTX: cp.async / ldmatrix / mma.sync)
// ---------------------------------------------------------------------------
__device__ __forceinline__ uint32_t smem_u32(const void* p) {
    uint32_t a;
    asm("{ .reg .u64 t; cvta.to.shared.u64 t, %1; cvt.u32.u64 %0, t; }" : "=r"(a) : "l"(p));
    return a;
}
__device__ __forceinline__ void cp16(uint32_t s, const void* g) {
    asm volatile("cp.async.cg.shared.global [%0], [%1], 16;" :: "r"(s), "l"(g));
}
__device__ __forceinline__ void ldsm_x4(uint32_t (&r)[4], uint32_t a) {
    asm volatile("ldmatrix.sync.aligned.m8n8.x4.shared.b16 {%0,%1,%2,%3}, [%4];"
                 : "=r"(r[0]), "=r"(r[1]), "=r"(r[2]), "=r"(r[3]) : "r"(a));
}
__device__ __forceinline__ void ldsm_x4t(uint32_t (&r)[4], uint32_t a) {
    asm volatile("ldmatrix.sync.aligned.m8n8.x4.trans.shared.b16 {%0,%1,%2,%3}, [%4];"
                 : "=r"(r[0]), "=r"(r[1]), "=r"(r[2]), "=r"(r[3]) : "r"(a));
}
__device__ __forceinline__ void mma_bf16(float (&c)[4], const uint32_t (&a)[4],
                                         uint32_t b0, uint32_t b1) {
    asm volatile("mma.sync.aligned.m16n8k16.row.col.f32.bf16.bf16.f32 "
                 "{%0,%1,%2,%3}, {%4,%5,%6,%7}, {%8,%9}, {%0,%1,%2,%3};"
                 : "+f"(c[0]), "+f"(c[1]), "+f"(c[2]), "+f"(c[3])
                 : "r"(a[0]), "r"(a[1]), "r"(a[2]), "r"(a[3]), "r"(b0), "r"(b1));
}
__device__ __forceinline__ uint32_t bfpack(float a, float b) {
    __nv_bfloat162 t = __floats2bfloat162_rn(a, b);
    return *reinterpret_cast<uint32_t*>(&t);
}
__device__ __forceinline__ float bfres(float a) {
    return a - __bfloat162float(__float2bfloat16(a));
}
// exp on the FMA/ALU pipes (no MUFU). Valid for x <= 0; flushes to ~0 below -87.
__device__ __forceinline__ float fexp(float x) {
    float y = x * 1.4426950408889634f;
    y = fmaxf(y, -126.0f);
    float t = y + 12582912.0f;            // round-to-nearest-int (magic)
    int   i = __float_as_int(t);
    float f = y - (t - 12582912.0f);      // frac in [-0.5, 0.5]
    float p = fmaf(f, 9.6181291076e-3f, 5.5504108664e-2f);
    p = fmaf(f, p, 2.4022650696e-1f);
    p = fmaf(f, p, 6.9314718056e-1f);
    p = fmaf(f, p, 1.0f);
    return p * __int_as_float((i + 127) << 23);
}

// ---------------------------------------------------------------------------
// Conversions (compact hi|lo)
// ---------------------------------------------------------------------------
__global__ void conv_split(const float* __restrict__ xin) {
    size_t idx = (size_t)blockIdx.x * 256 + threadIdx.x;
    int m = (int)(idx >> 10), kk = (int)(idx & 1023);
    float v = xin[idx];
    __nv_bfloat16 hi = __float2bfloat16(v);
    __nv_bfloat16 lo = __float2bfloat16(v - __bfloat162float(hi));
    __nv_bfloat16* row = g_xs + (size_t)m * KC;
    row[kk] = hi; row[1024 + kk] = lo;
}

// W[K,N] -> g_ws[z][N][wh|wl]
__global__ void conv_w(const float* __restrict__ W0, const float* __restrict__ W1,
                       const float* __restrict__ W2, const float* __restrict__ W3) {
    __shared__ float t[32][33];
    const int z = blockIdx.z;
    const float* W = (z == 0) ? W0 : (z == 1) ? W1 : (z == 2) ? W2 : W3;
    __nv_bfloat16* O = g_ws[z];
    int tx = threadIdx.x, ty = threadIdx.y;
    int k0 = blockIdx.y * 32, n0 = blockIdx.x * 32;
#pragma unroll
    for (int i = 0; i < 4; i++) {
        int kk = ty * 4 + i;
        t[kk][tx] = W[(size_t)(k0 + kk) * DD + n0 + tx];
    }
    __syncthreads();
#pragma unroll
    for (int i = 0; i < 4; i++) {
        int n = n0 + ty * 4 + i;
        int k = k0 + tx;
        float v = t[tx][ty * 4 + i];
        __nv_bfloat16 hi = __float2bfloat16(v);
        __nv_bfloat16 lo = __float2bfloat16(v - __bfloat162float(hi));
        __nv_bfloat16* row = O + (size_t)n * KC;
        row[k] = hi; row[1024 + k] = lo;
    }
}

// ---------------------------------------------------------------------------
// mma.sync bf16 GEMM with in-register compensation:
//   C = Ah*Bh + Ah*Bl + Al*Bh  over K=1024 logical, hi/lo frags reused.
// 128x128 CTA, 8 warps, K-chunk 32, 2-stage cp.async on 4 tiles (Ah/Al/Bh/Bl).
// B frags via ldmatrix.x4 (two ni-pairs per load).
// MODE 0: A=g_xs, B=g_ws[z]; epilogue splits into g_qx/g_kx/g_vx (bf16 hi/lo)
// MODE 1: A=g_zs, B=g_ws[3]; epilogue = Cout + bias (fp32)
// ---------------------------------------------------------------------------
#define GBK 32
#define NCH (1024 / GBK)        // 32 iterations
#define TPAD 40                 // elements per tile row (80 B)
#define TSTG (128 * TPAD * 2)   // bytes per tile per stage = 10240
#define GSMEM (8 * TSTG)        // 4 tiles x 2 stages = 81920

template<int MODE>
__global__ __launch_bounds__(256, 2)
void mma_gemm(const float* __restrict__ bias, float* __restrict__ Cout) {
    extern __shared__ __align__(16) char gs[];
    const uint32_t sAh = smem_u32(gs);
    const uint32_t sAl = sAh + 2 * TSTG;
    const uint32_t sBh = sAh + 4 * TSTG;
    const uint32_t sBl = sAh + 6 * TSTG;

    const int tid = threadIdx.x;
    const int wid = tid >> 5, lane = tid & 31;
    const int wm = wid >> 2;
    const int wn = wid & 3;

    const __nv_bfloat16* A = (MODE == 0) ? g_xs : g_zs;
    const __nv_bfloat16* B = (MODE == 0) ? g_ws[blockIdx.z] : g_ws[3];
    const __nv_bfloat16* Ab = A + (size_t)blockIdx.y * 128 * KC;
    const __nv_bfloat16* Bb = B + (size_t)blockIdx.x * 128 * KC;

    const int lr0 = tid >> 2, lr1 = (tid + 256) >> 2;
    const int lce = (tid & 3) * 8;
    const int lcb = lce * 2;

    // ldmatrix lane maps (A: x4 over 16 rows x 16 cols; B: x4 over 16 rows x 16 cols)
    const int ra = lane & 15, ca = (lane >> 4) << 3;
    const int rb2 = (lane & 7) + ((lane >> 1) & 8), cb2 = lane & 8;

    float acc[4][4][4];
#pragma unroll
    for (int i = 0; i < 4; i++)
#pragma unroll
        for (int j = 0; j < 4; j++)
#pragma unroll
            for (int v = 0; v < 4; v++) acc[i][j][v] = 0.f;

    auto load_chunk = [&](int chunk, int s) {
        const __nv_bfloat16* Ah = Ab + chunk * GBK;
        const __nv_bfloat16* Al = Ah + 1024;
        const __nv_bfloat16* Bh = Bb + chunk * GBK;
        const __nv_bfloat16* Bl = Bh + 1024;
        uint32_t o0 = s * TSTG + lr0 * (TPAD * 2) + lcb;
        uint32_t o1 = s * TSTG + lr1 * (TPAD * 2) + lcb;
        cp16(sAh + o0, Ah + (size_t)lr0 * KC + lce);
        cp16(sAh + o1, Ah + (size_t)lr1 * KC + lce);
        cp16(sAl + o0, Al + (size_t)lr0 * KC + lce);
        cp16(sAl + o1, Al + (size_t)lr1 * KC + lce);
        cp16(sBh + o0, Bh + (size_t)lr0 * KC + lce);
        cp16(sBh + o1, Bh + (size_t)lr1 * KC + lce);
        cp16(sBl + o0, Bl + (size_t)lr0 * KC + lce);
        cp16(sBl + o1, Bl + (size_t)lr1 * KC + lce);
    };

    load_chunk(0, 0);
    asm volatile("cp.async.commit_group;");

    for (int i = 0; i < NCH; i++) {
        const int s = i & 1;
        if (i + 1 < NCH) {
            load_chunk(i + 1, (i + 1) & 1);
            asm volatile("cp.async.commit_group;");
            asm volatile("cp.async.wait_group 1;");
        } else {
            asm volatile("cp.async.wait_group 0;");
        }
        __syncthreads();

#pragma unroll
        for (int k0 = 0; k0 < GBK; k0 += 16) {
            const uint32_t aoff = (uint32_t)(((wm * 64 + ra) * TPAD + k0 + ca) * 2) + s * TSTG;
            uint32_t ah[4][4], al[4][4];
#pragma unroll
            for (int mi = 0; mi < 4; mi++) {
                ldsm_x4(ah[mi], sAh + aoff + mi * (16 * TPAD * 2));
                ldsm_x4(al[mi], sAl + aoff + mi * (16 * TPAD * 2));
            }
            const uint32_t boff = (uint32_t)(((wn * 32 + rb2) * TPAD + k0 + cb2) * 2) + s * TSTG;
#pragma unroll
            for (int pp = 0; pp < 2; pp++) {
                uint32_t bh4[4], bl4[4];
                ldsm_x4(bh4, sBh + boff + pp * (16 * TPAD * 2));
                ldsm_x4(bl4, sBl + boff + pp * (16 * TPAD * 2));
#pragma unroll
                for (int mi = 0; mi < 4; mi++) {
                    mma_bf16(acc[mi][2 * pp], ah[mi], bh4[0], bh4[1]);
                    mma_bf16(acc[mi][2 * pp], ah[mi], bl4[0], bl4[1]);
                    mma_bf16(acc[mi][2 * pp], al[mi], bh4[0], bh4[1]);
                    mma_bf16(acc[mi][2 * pp + 1], ah[mi], bh4[2], bh4[3]);
                    mma_bf16(acc[mi][2 * pp + 1], ah[mi], bl4[2], bl4[3]);
                    mma_bf16(acc[mi][2 * pp + 1], al[mi], bh4[2], bh4[3]);
                }
            }
        }
        __syncthreads();
    }

    // Epilogue
    const int qr = lane >> 2, qc = (lane & 3) * 2;
#pragma unroll
    for (int mi = 0; mi < 4; mi++) {
#pragma unroll
        for (int ni = 0; ni < 4; ni++) {
            int col  = blockIdx.x * 128 + wn * 32 + ni * 8 + qc;
            int row0 = blockIdx.y * 128 + wm * 64 + mi * 16 + qr;
            int row1 = row0 + 8;
            float v0 = acc[mi][ni][0], v1 = acc[mi][ni][1];
            float v2 = acc[mi][ni][2], v3 = acc[mi][ni][3];
            if (MODE == 0) {
                const int z = blockIdx.z;
                if (z == 0) { v0 *= 0.125f; v1 *= 0.125f; v2 *= 0.125f; v3 *= 0.125f; }
                int h = col >> 6, hd = col & 63;
                int b0 = row0 >> 11, s0 = row0 & (SS - 1);
                int b1 = row1 >> 11, s1 = row1 & (SS - 1);
                int bh0 = b0 * NH + h, bh1 = b1 * NH + h;
                uint32_t H01 = bfpack(v0, v1), L01 = bfpack(bfres(v0), bfres(v1));
                uint32_t H23 = bfpack(v2, v3), L23 = bfpack(bfres(v2), bfres(v3));
                if (z == 0) {
                    __nv_bfloat16* p0 = g_qx + ((size_t)bh0 * SS + s0) * 128 + hd;
                    __nv_bfloat16* p1 = g_qx + ((size_t)bh1 * SS + s1) * 128 + hd;
                    *(uint32_t*)p0 = H01; *(uint32_t*)(p0 + 64) = L01;
                    *(uint32_t*)p1 = H23; *(uint32_t*)(p1 + 64) = L23;
                } else if (z == 1) {
                    __nv_bfloat16* p0 = g_kx + ((size_t)bh0 * SS + s0) * 128 + hd;
                    __nv_bfloat16* p1 = g_kx + ((size_t)bh1 * SS + s1) * 128 + hd;
                    *(uint32_t*)p0 = H01; *(uint32_t*)(p0 + 64) = L01;
                    *(uint32_t*)p1 = H23; *(uint32_t*)(p1 + 64) = L23;
                } else {
                    __nv_bfloat16* p0 = g_vx + ((size_t)bh0 * 2 * SS + s0) * HD + hd;
                    __nv_bfloat16* p1 = g_vx + ((size_t)bh1 * 2 * SS + s1) * HD + hd;
                    *(uint32_t*)p0 = H01; *(uint32_t*)(p0 + SS * HD) = L01;
                    *(uint32_t*)p1 = H23; *(uint32_t*)(p1 + SS * HD) = L23;
                }
            } else {
                float bx0 = bias[col], bx1 = bias[col + 1];
                *(float2*)(Cout + (size_t)row0 * DD + col) = make_float2(v0 + bx0, v1 + bx1);
                *(float2*)(Cout + (size_t)row1 * DD + col) = make_float2(v2 + bx0, v3 + bx1);
            }
        }
    }
}

// ---------------------------------------------------------------------------
// Flash attention on mma.sync. 64 q-rows/CTA, 4 warps. Deferred l-reduction
// (per-lane partials; single shuffle-reduce in epilogue).
// ---------------------------------------------------------------------------
#define QKSTR 272          // bytes per Q/K smem row (128 bf16 + pad)
#define VSTR 144           // bytes per V smem row
#define QTB 17408
#define KTB 17408
#define VTB 18432
#define FSMEM (QTB + KTB + VTB)   // 53248

__global__ __launch_bounds__(128, 3)
void flash_mma() {
    extern __shared__ __align__(16) char fs[];
    const uint32_t qbuf = smem_u32(fs);
    const uint32_t kbuf = qbuf + QTB;
    const uint32_t vbuf = kbuf + KTB;
    const int tid = threadIdx.x, w = tid >> 5, lane = tid & 31;
    const int qb = gridDim.x - 1 - blockIdx.x;    // heavy CTAs first
    const int bh = blockIdx.y;

    const __nv_bfloat16* Qg = g_qx + ((size_t)bh * SS + qb * 64) * 128;
    const __nv_bfloat16* Kg = g_kx + (size_t)bh * SS * 128;
    const __nv_bfloat16* Vg = g_vx + (size_t)bh * 2 * SS * HD;

    const int ra = lane & 15, ca = (lane >> 4) << 3;
    const int rb = (lane & 7) + ((lane >> 1) & 8), cb = lane & 8;
    const int rv = lane & 15, cv = (lane >> 4) << 3;

#pragma unroll
    for (int t = 0; t < 8; t++) {
        int idx = tid + t * 128;
        int r = idx >> 4, c = idx & 15;
        cp16(qbuf + r * QKSTR + c * 16, Qg + (size_t)r * 128 + c * 8);
    }
    asm volatile("cp.async.commit_group;");
    asm volatile("cp.async.wait_group 0;");
    __syncthreads();
    uint32_t qfr[8][4];
#pragma unroll
    for (int k = 0; k < 8; k++)
        ldsm_x4(qfr[k], qbuf + (16 * w + ra) * QKSTR + (k * 16 + ca) * 2);

    float m0 = -1e30f, m1 = -1e30f, l0 = 0.f, l1 = 0.f;   // l = per-lane partials
    float o[8][4];
#pragma unroll
    for (int j = 0; j < 8; j++)
#pragma unroll
        for (int v = 0; v < 4; v++) o[j][v] = 0.f;

    for (int kt = 0; kt <= qb; kt++) {
#pragma unroll
        for (int t = 0; t < 8; t++) {
            int idx = tid + t * 128;
            int r = idx >> 4, c = idx & 15;
            cp16(kbuf + r * QKSTR + c * 16, Kg + (size_t)(kt * 64 + r) * 128 + c * 8);
        }
#pragma unroll
        for (int t = 0; t < 8; t++) {
            int idx = tid + t * 128;
            int r = idx >> 3, c = idx & 7;
            int grow = (r >> 6) * SS + kt * 64 + (r & 63);
            cp16(vbuf + r * VSTR + c * 16, Vg + (size_t)grow * HD + c * 8);
        }
        asm volatile("cp.async.commit_group;");
        asm volatile("cp.async.wait_group 0;");
        __syncthreads();

        float sf[8][4];
#pragma unroll
        for (int j = 0; j < 8; j++)
#pragma unroll
            for (int v = 0; v < 4; v++) sf[j][v] = 0.f;
#pragma unroll
        for (int jj = 0; jj < 4; jj++) {
            uint32_t kf[4][4];
#pragma unroll
            for (int t = 0; t < 4; t++)
                ldsm_x4(kf[t], kbuf + (16 * jj + rb) * QKSTR + (t * 16 + cb) * 2);
#pragma unroll
            for (int lk = 0; lk < 4; lk++) {
                mma_bf16(sf[2 * jj],     qfr[lk], kf[lk][0], kf[lk][1]);
                mma_bf16(sf[2 * jj + 1], qfr[lk], kf[lk][2], kf[lk][3]);
            }
#pragma unroll
            for (int lk = 4; lk < 8; lk++) {
                uint32_t r4[4];
                ldsm_x4(r4, kbuf + (16 * jj + rb) * QKSTR + (lk * 16 + cb) * 2);
                mma_bf16(sf[2 * jj],     qfr[lk - 4], r4[0], r4[1]);
                mma_bf16(sf[2 * jj + 1], qfr[lk - 4], r4[2], r4[3]);
            }
#pragma unroll
            for (int lk = 8; lk < 12; lk++) {
                mma_bf16(sf[2 * jj],     qfr[lk - 4], kf[lk - 8][0], kf[lk - 8][1]);
                mma_bf16(sf[2 * jj + 1], qfr[lk - 4], kf[lk - 8][2], kf[lk - 8][3]);
            }
        }

        if (kt == qb) {
            int row0 = 16 * w + (lane >> 2);
#pragma unroll
            for (int j = 0; j < 8; j++) {
                int key = 8 * j + 2 * (lane & 3);
                if (key     > row0)     sf[j][0] = -1e30f;
                if (key + 1 > row0)     sf[j][1] = -1e30f;
                if (key     > row0 + 8) sf[j][2] = -1e30f;
                if (key + 1 > row0 + 8) sf[j][3] = -1e30f;
            }
        }

        float tm0 = -1e30f, tm1 = -1e30f;
#pragma unroll
        for (int j = 0; j < 8; j++) {
            tm0 = fmaxf(tm0, fmaxf(sf[j][0], sf[j][1]));
            tm1 = fmaxf(tm1, fmaxf(sf[j][2], sf[j][3]));
        }
        tm0 = fmaxf(tm0, __shfl_xor_sync(0xffffffffu, tm0, 1));
        tm0 = fmaxf(tm0, __shfl_xor_sync(0xffffffffu, tm0, 2));
        tm1 = fmaxf(tm1, __shfl_xor_sync(0xffffffffu, tm1, 1));
        tm1 = fmaxf(tm1, __shfl_xor_sync(0xffffffffu, tm1, 2));
        float mn0 = fmaxf(m0, tm0), mn1 = fmaxf(m1, tm1);
        float c0 = fexp(m0 - mn0), c1 = fexp(m1 - mn1);
        m0 = mn0; m1 = mn1;

        float s0 = 0.f, s1 = 0.f;
        uint32_t ph[4][4], pl[4][4];
#pragma unroll
        for (int t = 0; t < 4; t++) {
            float pa = fexp(sf[2 * t][0] - mn0),     pb = fexp(sf[2 * t][1] - mn0);
            float pc = fexp(sf[2 * t][2] - mn1),     pd = fexp(sf[2 * t][3] - mn1);
            float pe = fexp(sf[2 * t + 1][0] - mn0), pf = fexp(sf[2 * t + 1][1] - mn0);
            float pg = fexp(sf[2 * t + 1][2] - mn1), pq = fexp(sf[2 * t + 1][3] - mn1);
            s0 += (pa + pb) + (pe + pf);
            s1 += (pc + pd) + (pg + pq);
            ph[t][0] = bfpack(pa, pb); pl[t][0] = bfpack(bfres(pa), bfres(pb));
            ph[t][1] = bfpack(pc, pd); pl[t][1] = bfpack(bfres(pc), bfres(pd));
            ph[t][2] = bfpack(pe, pf); pl[t][2] = bfpack(bfres(pe), bfres(pf));
            ph[t][3] = bfpack(pg, pq); pl[t][3] = bfpack(bfres(pg), bfres(pq));
        }
        // deferred: per-lane partial update, no shuffles here
        l0 = l0 * c0 + s0;
        l1 = l1 * c1 + s1;
#pragma unroll
        for (int j = 0; j < 8; j++) {
            o[j][0] *= c0; o[j][1] *= c0; o[j][2] *= c1; o[j][3] *= c1;
        }

#pragma unroll
        for (int jj = 0; jj < 4; jj++) {
            uint32_t vf[4][4];
#pragma unroll
            for (int t = 0; t < 4; t++)
                ldsm_x4t(vf[t], vbuf + (t * 16 + rv) * VSTR + (jj * 16 + cv) * 2);
#pragma unroll
            for (int kc = 0; kc < 4; kc++) {
                mma_bf16(o[2 * jj],     ph[kc], vf[kc][0], vf[kc][1]);
                mma_bf16(o[2 * jj + 1], ph[kc], vf[kc][2], vf[kc][3]);
            }
#pragma unroll
            for (int kc = 4; kc < 8; kc++) {
                uint32_t r4[4];
                ldsm_x4t(r4, vbuf + (kc * 16 + rv) * VSTR + (jj * 16 + cv) * 2);
                mma_bf16(o[2 * jj],     ph[kc - 4], r4[0], r4[1]);
                mma_bf16(o[2 * jj + 1], ph[kc - 4], r4[2], r4[3]);
            }
#pragma unroll
            for (int kc = 8; kc < 12; kc++) {
                mma_bf16(o[2 * jj],     pl[kc - 8], vf[kc - 8][0], vf[kc - 8][1]);
                mma_bf16(o[2 * jj + 1], pl[kc - 8], vf[kc - 8][2], vf[kc - 8][3]);
            }
        }
        __syncthreads();
    }

    // ---- final l reduction (deferred shuffles) ----
    l0 += __shfl_xor_sync(0xffffffffu, l0, 1);
    l0 += __shfl_xor_sync(0xffffffffu, l0, 2);
    l1 += __shfl_xor_sync(0xffffffffu, l1, 1);
    l1 += __shfl_xor_sync(0xffffffffu, l1, 2);

    // ---- epilogue: write z split (compact) into g_zs ----
    float i0 = 1.f / l0, i1 = 1.f / l1;
    int b = bh >> 4, h = bh & 15;
    int srow = qb * 64 + 16 * w + (lane >> 2);
    __nv_bfloat16* z0 = g_zs + (size_t)(b * SS + srow) * KC;
    __nv_bfloat16* z1 = g_zs + (size_t)(b * SS + srow + 8) * KC;
    int kk = h * 64 + 2 * (lane & 3);
#pragma unroll
    for (int j = 0; j < 8; j++) {
        int col = kk + 8 * j;
        float v0 = o[j][0] * i0, v1 = o[j][1] * i0;
        float v2 = o[j][2] * i1, v3 = o[j][3] * i1;
        uint32_t H0 = bfpack(v0, v1), L0 = bfpack(bfres(v0), bfres(v1));
        uint32_t H1 = bfpack(v2, v3), L1 = bfpack(bfres(v2), bfres(v3));
        *(uint32_t*)(z0 + col) = H0; *(uint32_t*)(z0 + 1024 + col) = L0;
        *(uint32_t*)(z1 + col) = H1; *(uint32_t*)(z1 + 1024 + col) = L1;
    }
}

// ---------------------------------------------------------------------------
extern "C" void kernel_launch(void* const* d_in, const int* in_sizes, int n_in,
                              void* d_out, int out_size)
{
    const float* x  = (const float*)d_in[0];
    const float* Wq = (const float*)d_in[1];
    const float* Wk = (const float*)d_in[2];
    const float* Wv = (const float*)d_in[3];
    const float* Wo = (const float*)d_in[4];
    const float* bo = (const float*)d_in[5];
    float* out = (float*)d_out;

    cudaFuncSetAttribute(flash_mma, cudaFuncAttributeMaxDynamicSharedMemorySize, FSMEM);
    cudaFuncSetAttribute(mma_gemm<0>, cudaFuncAttributeMaxDynamicSharedMemorySize, GSMEM);
    cudaFuncSetAttribute(mma_gemm<1>, cudaFuncAttributeMaxDynamicSharedMemorySize, GSMEM);

    conv_split<<<(size_t)MM * DD / 256, 256>>>(x);
    conv_w<<<dim3(32, 32, 4), dim3(32, 8)>>>(Wq, Wk, Wv, Wo);

    mma_gemm<0><<<dim3(8, 32, 3), 256, GSMEM>>>(nullptr, nullptr);

    flash_mma<<<dim3(SS / 64, NB * NH), 128, FSMEM>>>();

    mma_gemm<1><<<dim3(8, 32), 256, GSMEM>>>(bo, out);
}